// round 11
// baseline (speedup 1.0000x reference)
#include <cuda_runtime.h>

// Problem constants
#define BB   2
#define SDIM 2048
#define DD   1024
#define HH   16
#define DKK  64

// Scratch (device globals; no allocations allowed)
__device__ float g_q[BB * SDIM * DD];
__device__ float g_k[BB * SDIM * DD];
__device__ float g_v[BB * SDIM * DD];
__device__ float g_ctx[BB * SDIM * DD];

// ---------------------------------------------------------------------------
// TF32 helpers
// ---------------------------------------------------------------------------
__device__ __forceinline__ unsigned f2tf(float f) {
    unsigned u;
    asm("cvt.rna.tf32.f32 %0, %1;" : "=r"(u) : "f"(f));
    return u;
}

template <bool C>
__device__ __forceinline__ unsigned tfbits(float f) {
    return C ? f2tf(f) : __float_as_uint(f);
}

__device__ __forceinline__ void mma4(float* c,
                                     unsigned a0, unsigned a1, unsigned a2, unsigned a3,
                                     unsigned b0, unsigned b1) {
    asm volatile(
        "mma.sync.aligned.m16n8k8.row.col.f32.tf32.tf32.f32 "
        "{%0,%1,%2,%3}, {%4,%5,%6,%7}, {%8,%9}, {%0,%1,%2,%3};"
        : "+f"(c[0]), "+f"(c[1]), "+f"(c[2]), "+f"(c[3])
        : "r"(a0), "r"(a1), "r"(a2), "r"(a3), "r"(b0), "r"(b1));
}

// ---------------------------------------------------------------------------
// Shared layouts (BK = 16).
//
// QUAD layout (LDS.128 fragment loads, conflict-free STS.64 writes):
//   k -> row = (k&3) + ((k>>3)<<2), kh = (k>>2)&1
//   word(m,k) = row*RSTR + ((m>>4)<<5) + ((m&7)<<2) + (((m>>3)&1)<<1) + kh
//   uint4 at row*RSTR + m16*2 + g*4 = {(m0,k),(m0,k+4),(m0+8,k),(m0+8,k+4)}
//
// PAIR layout (B of NN gemm; LDS.64 loads, XOR-swizzled low-conflict writes):
//   word = ((k>>3)*4 + (k&3))*PSTR + bsw(n, (k>>2)&1)
// ---------------------------------------------------------------------------
#define RSTR  264
#define PSTR  264
#define PSTRC 136

__device__ __forceinline__ int mwp(int m) {
    return ((m >> 4) << 5) + ((m & 7) << 2) + (((m >> 3) & 1) << 1);
}

template <bool C>
__device__ __forceinline__ void store_op(unsigned* S, int ak, int m,
                                         float4 p0, float4 p1) {
    unsigned* b = S + ((ak >> 3) << 2) * RSTR + mwp(m);
    *(uint2*)(b + 0 * RSTR) = make_uint2(tfbits<C>(p0.x), tfbits<C>(p1.x));
    *(uint2*)(b + 1 * RSTR) = make_uint2(tfbits<C>(p0.y), tfbits<C>(p1.y));
    *(uint2*)(b + 2 * RSTR) = make_uint2(tfbits<C>(p0.z), tfbits<C>(p1.z));
    *(uint2*)(b + 3 * RSTR) = make_uint2(tfbits<C>(p0.w), tfbits<C>(p1.w));
}

__device__ __forceinline__ int bsw(int n, int q) {
    int w = n * 2 + q;
    w ^= ((w >> 5) & 7) << 1;
    return w;
}

// ---------------------------------------------------------------------------
// TF32 GEMM NN: C = A(MxK) * B(KxN). BM=BN=128, BK=16, double-buffered.
// 128 threads = 4 warps as 2(m) x 2(n); warp tile 64x64.
// ---------------------------------------------------------------------------
template <bool CA, bool CB, bool RO>
__global__ __launch_bounds__(128, 2)
void gemm_tf32_nn(const float* __restrict__ A, const float* __restrict__ B,
                  float* __restrict__ C, int M, int N, int K)
{
    __shared__ unsigned As[2][8 * RSTR];
    __shared__ unsigned Bs[2][8 * PSTR];

    const int tid  = threadIdx.x;
    const int lane = tid & 31;
    const int warp = tid >> 5;
    const int g    = lane >> 2;
    const int tg   = lane & 3;
    const int wm   = (warp >> 1) * 64;
    const int wn   = (warp & 1) * 64;

    const int am  = tid;                    // A: one row per thread, 16 k
    const int bk0 = (tid >> 4) * 2;         // B: two k-rows, 8 cols each
    const int bn  = (tid & 15) * 8;
    const int bp0 = ((bk0 >> 3) * 4 + (bk0 & 3)) * PSTR;
    const int bq0 = (bk0 >> 2) & 1;
    const int bk1 = bk0 + 1;
    const int bp1 = ((bk1 >> 3) * 4 + (bk1 & 3)) * PSTR;
    const int bq1 = (bk1 >> 2) & 1;

    const float* Ap = A + (size_t)(blockIdx.y * 128 + am) * K;
    const float* Bp = B + (size_t)bk0 * N + blockIdx.x * 128 + bn;

    float4 pa[4], pb[4];
    #pragma unroll
    for (int j = 0; j < 4; ++j) pa[j] = *(const float4*)(Ap + 4 * j);
    pb[0] = *(const float4*)Bp;
    pb[1] = *(const float4*)(Bp + 4);
    pb[2] = *(const float4*)(Bp + N);
    pb[3] = *(const float4*)(Bp + N + 4);

    float c[32][4];
    #pragma unroll
    for (int i = 0; i < 32; ++i)
        #pragma unroll
        for (int j = 0; j < 4; ++j) c[i][j] = 0.f;

    // stage buffer 0
    store_op<CA>(As[0], 0, am, pa[0], pa[1]);
    store_op<CA>(As[0], 8, am, pa[2], pa[3]);
    {
        unsigned* b0 = Bs[0] + bp0;
        b0[bsw(bn + 0, bq0)] = tfbits<CB>(pb[0].x);
        b0[bsw(bn + 1, bq0)] = tfbits<CB>(pb[0].y);
        b0[bsw(bn + 2, bq0)] = tfbits<CB>(pb[0].z);
        b0[bsw(bn + 3, bq0)] = tfbits<CB>(pb[0].w);
        b0[bsw(bn + 4, bq0)] = tfbits<CB>(pb[1].x);
        b0[bsw(bn + 5, bq0)] = tfbits<CB>(pb[1].y);
        b0[bsw(bn + 6, bq0)] = tfbits<CB>(pb[1].z);
        b0[bsw(bn + 7, bq0)] = tfbits<CB>(pb[1].w);
        unsigned* b1 = Bs[0] + bp1;
        b1[bsw(bn + 0, bq1)] = tfbits<CB>(pb[2].x);
        b1[bsw(bn + 1, bq1)] = tfbits<CB>(pb[2].y);
        b1[bsw(bn + 2, bq1)] = tfbits<CB>(pb[2].z);
        b1[bsw(bn + 3, bq1)] = tfbits<CB>(pb[2].w);
        b1[bsw(bn + 4, bq1)] = tfbits<CB>(pb[3].x);
        b1[bsw(bn + 5, bq1)] = tfbits<CB>(pb[3].y);
        b1[bsw(bn + 6, bq1)] = tfbits<CB>(pb[3].z);
        b1[bsw(bn + 7, bq1)] = tfbits<CB>(pb[3].w);
    }
    __syncthreads();

    const int iters = K >> 4;
    for (int it = 0; it < iters; ++it) {
        const int cur = it & 1;
        const bool more = (it + 1 < iters);
        if (more) {
            Ap += 16; Bp += (size_t)16 * N;
            #pragma unroll
            for (int j = 0; j < 4; ++j) pa[j] = *(const float4*)(Ap + 4 * j);
            pb[0] = *(const float4*)Bp;
            pb[1] = *(const float4*)(Bp + 4);
            pb[2] = *(const float4*)(Bp + N);
            pb[3] = *(const float4*)(Bp + N + 4);
        }

        #pragma unroll
        for (int ks = 0; ks < 2; ++ks) {
            const unsigned* Ar = As[cur] + (ks * 4 + tg) * RSTR + (g << 2);
            const unsigned* Br = Bs[cur] + (ks * 4 + tg) * PSTR;
            uint4 A0 = *(const uint4*)(Ar + wm * 2);
            uint4 A1 = *(const uint4*)(Ar + (wm + 16) * 2);
            uint4 A2 = *(const uint4*)(Ar + (wm + 32) * 2);
            uint4 A3 = *(const uint4*)(Ar + (wm + 48) * 2);
            #pragma unroll
            for (int ni = 0; ni < 8; ++ni) {
                int w = (wn + ni * 8 + g) * 2;
                w ^= ((w >> 5) & 7) << 1;
                uint2 bv = *(const uint2*)(Br + w);
                mma4(c[ni],      A0.x, A0.z, A0.y, A0.w, bv.x, bv.y);
                mma4(c[8 + ni],  A1.x, A1.z, A1.y, A1.w, bv.x, bv.y);
                mma4(c[16 + ni], A2.x, A2.z, A2.y, A2.w, bv.x, bv.y);
                mma4(c[24 + ni], A3.x, A3.z, A3.y, A3.w, bv.x, bv.y);
            }
        }

        if (more) {
            store_op<CA>(As[1 - cur], 0, am, pa[0], pa[1]);
            store_op<CA>(As[1 - cur], 8, am, pa[2], pa[3]);
            unsigned* b0 = Bs[1 - cur] + bp0;
            b0[bsw(bn + 0, bq0)] = tfbits<CB>(pb[0].x);
            b0[bsw(bn + 1, bq0)] = tfbits<CB>(pb[0].y);
            b0[bsw(bn + 2, bq0)] = tfbits<CB>(pb[0].z);
            b0[bsw(bn + 3, bq0)] = tfbits<CB>(pb[0].w);
            b0[bsw(bn + 4, bq0)] = tfbits<CB>(pb[1].x);
            b0[bsw(bn + 5, bq0)] = tfbits<CB>(pb[1].y);
            b0[bsw(bn + 6, bq0)] = tfbits<CB>(pb[1].z);
            b0[bsw(bn + 7, bq0)] = tfbits<CB>(pb[1].w);
            unsigned* b1 = Bs[1 - cur] + bp1;
            b1[bsw(bn + 0, bq1)] = tfbits<CB>(pb[2].x);
            b1[bsw(bn + 1, bq1)] = tfbits<CB>(pb[2].y);
            b1[bsw(bn + 2, bq1)] = tfbits<CB>(pb[2].z);
            b1[bsw(bn + 3, bq1)] = tfbits<CB>(pb[2].w);
            b1[bsw(bn + 4, bq1)] = tfbits<CB>(pb[3].x);
            b1[bsw(bn + 5, bq1)] = tfbits<CB>(pb[3].y);
            b1[bsw(bn + 6, bq1)] = tfbits<CB>(pb[3].z);
            b1[bsw(bn + 7, bq1)] = tfbits<CB>(pb[3].w);
            __syncthreads();
        }
    }

    #pragma unroll
    for (int mi = 0; mi < 4; ++mi) {
        #pragma unroll
        for (int ni = 0; ni < 8; ++ni) {
            const float* cc = c[mi * 8 + ni];
            const int row = blockIdx.y * 128 + wm + mi * 16 + g;
            const int col = blockIdx.x * 128 + wn + ni * 8 + 2 * tg;
            float v0 = cc[0], v1 = cc[1], v2 = cc[2], v3 = cc[3];
            if (RO) {
                v0 = __uint_as_float(f2tf(v0));
                v1 = __uint_as_float(f2tf(v1));
                v2 = __uint_as_float(f2tf(v2));
                v3 = __uint_as_float(f2tf(v3));
            }
            *(float2*)&C[(size_t)row * N + col]       = make_float2(v0, v1);
            *(float2*)&C[(size_t)(row + 8) * N + col] = make_float2(v2, v3);
        }
    }
}

// ---------------------------------------------------------------------------
// scores: attn[b,h,i,j] = (q.k)/8, causal mask by index, masked = -1e9.
// 128 threads, 4 warps 2x2, warp tile 64x64, both operands quad (LDS.128).
// ---------------------------------------------------------------------------
__global__ __launch_bounds__(128, 2)
void scores_tf32(const float* __restrict__ q, const float* __restrict__ k,
                 float* __restrict__ attn)
{
    const int bx = blockIdx.x;
    const int by = blockIdx.y;
    if (bx > by) return;
    const int z = blockIdx.z;
    const int b = z >> 4;
    const int h = z & 15;

    __shared__ unsigned As[2][8 * RSTR];
    __shared__ unsigned Bs[2][8 * RSTR];

    const int tid  = threadIdx.x;
    const int lane = tid & 31;
    const int warp = tid >> 5;
    const int g    = lane >> 2;
    const int tg   = lane & 3;
    const int wm   = (warp >> 1) * 64;
    const int wn   = (warp & 1) * 64;

    const int r = tid;

    const float* Ap = q + (size_t)(b * SDIM + by * 128 + r) * DD + h * DKK;
    const float* Bp = k + (size_t)(b * SDIM + bx * 128 + r) * DD + h * DKK;

    float4 pa[4], pb[4];
    #pragma unroll
    for (int j = 0; j < 4; ++j) {
        pa[j] = *(const float4*)(Ap + 4 * j);
        pb[j] = *(const float4*)(Bp + 4 * j);
    }

    float c[32][4];
    #pragma unroll
    for (int i = 0; i < 32; ++i)
        #pragma unroll
        for (int j = 0; j < 4; ++j) c[i][j] = 0.f;

    store_op<false>(As[0], 0, r, pa[0], pa[1]);
    store_op<false>(As[0], 8, r, pa[2], pa[3]);
    store_op<false>(Bs[0], 0, r, pb[0], pb[1]);
    store_op<false>(Bs[0], 8, r, pb[2], pb[3]);
    __syncthreads();

    for (int it = 0; it < 4; ++it) {
        const int cur = it & 1;
        const bool more = (it < 3);
        if (more) {
            Ap += 16; Bp += 16;
            #pragma unroll
            for (int j = 0; j < 4; ++j) {
                pa[j] = *(const float4*)(Ap + 4 * j);
                pb[j] = *(const float4*)(Bp + 4 * j);
            }
        }

        #pragma unroll
        for (int ks = 0; ks < 2; ++ks) {
            const unsigned* Ar = As[cur] + (ks * 4 + tg) * RSTR + (g << 2);
            const unsigned* Br = Bs[cur] + (ks * 4 + tg) * RSTR + (g << 2);
            uint4 A0 = *(const uint4*)(Ar + wm * 2);
            uint4 A1 = *(const uint4*)(Ar + (wm + 16) * 2);
            uint4 A2 = *(const uint4*)(Ar + (wm + 32) * 2);
            uint4 A3 = *(const uint4*)(Ar + (wm + 48) * 2);
            #pragma unroll
            for (int np = 0; np < 4; ++np) {
                uint4 Bv = *(const uint4*)(Br + (wn + np * 16) * 2);
                const int ni = np * 2;
                mma4(c[ni],          A0.x, A0.z, A0.y, A0.w, Bv.x, Bv.y);
                mma4(c[ni + 1],      A0.x, A0.z, A0.y, A0.w, Bv.z, Bv.w);
                mma4(c[8 + ni],      A1.x, A1.z, A1.y, A1.w, Bv.x, Bv.y);
                mma4(c[8 + ni + 1],  A1.x, A1.z, A1.y, A1.w, Bv.z, Bv.w);
                mma4(c[16 + ni],     A2.x, A2.z, A2.y, A2.w, Bv.x, Bv.y);
                mma4(c[16 + ni + 1], A2.x, A2.z, A2.y, A2.w, Bv.z, Bv.w);
                mma4(c[24 + ni],     A3.x, A3.z, A3.y, A3.w, Bv.x, Bv.y);
                mma4(c[24 + ni + 1], A3.x, A3.z, A3.y, A3.w, Bv.z, Bv.w);
            }
        }

        if (more) {
            store_op<false>(As[1 - cur], 0, r, pa[0], pa[1]);
            store_op<false>(As[1 - cur], 8, r, pa[2], pa[3]);
            store_op<false>(Bs[1 - cur], 0, r, pb[0], pb[1]);
            store_op<false>(Bs[1 - cur], 8, r, pb[2], pb[3]);
            __syncthreads();
        }
    }

    #pragma unroll
    for (int mi = 0; mi < 4; ++mi) {
        #pragma unroll
        for (int ni = 0; ni < 8; ++ni) {
            const float* cc = c[mi * 8 + ni];
            const int i0 = by * 128 + wm + mi * 16 + g;
            const int j0 = bx * 128 + wn + ni * 8 + 2 * tg;
            #pragma unroll
            for (int rr = 0; rr < 2; ++rr) {
                const int i = i0 + rr * 8;
                float2 o;
                o.x = (j0     > i) ? -1e9f : cc[rr * 2 + 0] * 0.125f;
                o.y = (j0 + 1 > i) ? -1e9f : cc[rr * 2 + 1] * 0.125f;
                *(float2*)&attn[((size_t)z * SDIM + i) * SDIM + j0] = o;
            }
        }
    }
}

// ---------------------------------------------------------------------------
// Row softmax in place over computed prefix [0, L); zero-fill [L, S).
// ---------------------------------------------------------------------------
__global__ __launch_bounds__(256)
void softmax_kernel(float* __restrict__ attn)
{
    __shared__ float redmax[8];
    __shared__ float redsum[8];

    const int r   = blockIdx.x;
    const int i   = r & (SDIM - 1);
    const int L   = ((i >> 7) + 1) << 7;
    const int tid = threadIdx.x;
    float* row = attn + (size_t)r * SDIM;

    float x[8];
    float m = -3.4e38f;
    #pragma unroll
    for (int t = 0; t < 8; ++t) {
        const int j = tid + t * 256;
        if (j < L) { x[t] = row[j]; m = fmaxf(m, x[t]); }
    }
    #pragma unroll
    for (int o = 16; o; o >>= 1) m = fmaxf(m, __shfl_xor_sync(0xffffffffu, m, o));
    if ((tid & 31) == 0) redmax[tid >> 5] = m;
    __syncthreads();
    if (tid == 0) {
        float t = redmax[0];
        #pragma unroll
        for (int w = 1; w < 8; ++w) t = fmaxf(t, redmax[w]);
        redmax[0] = t;
    }
    __syncthreads();
    const float M = redmax[0];

    float s = 0.f;
    #pragma unroll
    for (int t = 0; t < 8; ++t) {
        const int j = tid + t * 256;
        if (j < L) { x[t] = __expf(x[t] - M); s += x[t]; }
    }
    #pragma unroll
    for (int o = 16; o; o >>= 1) s += __shfl_xor_sync(0xffffffffu, s, o);
    if ((tid & 31) == 0) redsum[tid >> 5] = s;
    __syncthreads();
    if (tid == 0) {
        float t = 0.f;
        #pragma unroll
        for (int w = 0; w < 8; ++w) t += redsum[w];
        redsum[0] = t;
    }
    __syncthreads();
    const float inv = 1.f / redsum[0];

    #pragma unroll
    for (int t = 0; t < 8; ++t) {
        const int j = tid + t * 256;
        if (j < L) row[j] = x[t] * inv;
    }
    for (int j = L + tid; j < SDIM; j += 256) row[j] = 0.f;
}

// ---------------------------------------------------------------------------
// context: ctx[b,i,h*64+c] = sum_j attn[z,i,j] * v[b,j,h*64+c]
// attn quad-packed w/ cvt; v pair-packed (pre-rounded). Output tf32-rounded.
// ---------------------------------------------------------------------------
__global__ __launch_bounds__(256, 2)
void context_tf32(const float* __restrict__ attn, const float* __restrict__ v,
                  float* __restrict__ ctx)
{
    const int z = blockIdx.z;
    const int b = z >> 4;
    const int h = z & 15;
    const int i0 = blockIdx.y * 128;

    __shared__ unsigned As[2][8 * RSTR];
    __shared__ unsigned Bs[2][8 * PSTRC];

    const int tid  = threadIdx.x;
    const int lane = tid & 31;
    const int warp = tid >> 5;
    const int g    = lane >> 2;
    const int tg   = lane & 3;

    const int r  = tid >> 1, kq = (tid & 1) << 3;
    const int bk = tid >> 4, bc = (tid & 15) << 2;
    const int bp = ((bk >> 3) * 4 + (bk & 3)) * PSTRC;
    const int bq = (bk >> 2) & 1;

    const float* Ap = attn + ((size_t)z * SDIM + i0 + r) * SDIM + kq;
    const float* Bp = v + ((size_t)(b * SDIM) + bk) * DD + h * DKK + bc;

    float4 pa0 = *(const float4*)Ap;
    float4 pa1 = *(const float4*)(Ap + 4);
    float4 pb0 = *(const float4*)Bp;

    float c[8][4];
    #pragma unroll
    for (int i = 0; i < 8; ++i)
        #pragma unroll
        for (int j = 0; j < 4; ++j) c[i][j] = 0.f;

    store_op<true>(As[0], kq, r, pa0, pa1);
    {
        unsigned* bb = Bs[0] + bp;
        bb[bsw(bc + 0, bq)] = __float_as_uint(pb0.x);
        bb[bsw(bc + 1, bq)] = __float_as_uint(pb0.y);
        bb[bsw(bc + 2, bq)] = __float_as_uint(pb0.z);
        bb[bsw(bc + 3, bq)] = __float_as_uint(pb0.w);
    }
    __syncthreads();

    const int iters = (i0 + 128) >> 4;
    for (int it = 0; it < iters; ++it) {
        const int cur = it & 1;
        const bool more = (it + 1 < iters);
        if (more) {
            Ap += 16; Bp += (size_t)16 * DD;
            pa0 = *(const float4*)Ap;
            pa1 = *(const float4*)(Ap + 4);
            pb0 = *(const float4*)Bp;
        }

        #pragma unroll
        for (int ks = 0; ks < 2; ++ks) {
            const unsigned* Ar = As[cur] + (ks * 4 + tg) * RSTR + (g << 2);
            const unsigned* Br = Bs[cur] + (ks * 4 + tg) * PSTRC;
            uint4 A0 = *(const uint4*)(Ar + warp * 32);
            #pragma unroll
            for (int ni = 0; ni < 8; ++ni) {
                int w = (ni * 8 + g) * 2;
                w ^= ((w >> 5) & 7) << 1;
                uint2 bv = *(const uint2*)(Br + w);
                mma4(c[ni], A0.x, A0.z, A0.y, A0.w, bv.x, bv.y);
            }
        }

        if (more) {
            store_op<true>(As[1 - cur], kq, r, pa0, pa1);
            unsigned* bb = Bs[1 - cur] + bp;
            bb[bsw(bc + 0, bq)] = __float_as_uint(pb0.x);
            bb[bsw(bc + 1, bq)] = __float_as_uint(pb0.y);
            bb[bsw(bc + 2, bq)] = __float_as_uint(pb0.z);
            bb[bsw(bc + 3, bq)] = __float_as_uint(pb0.w);
            __syncthreads();
        }
    }

    #pragma unroll
    for (int ni = 0; ni < 8; ++ni) {
        const int row = i0 + warp * 16 + g;
        const int col = h * DKK + ni * 8 + 2 * tg;
        float v0 = __uint_as_float(f2tf(c[ni][0]));
        float v1 = __uint_as_float(f2tf(c[ni][1]));
        float v2 = __uint_as_float(f2tf(c[ni][2]));
        float v3 = __uint_as_float(f2tf(c[ni][3]));
        *(float2*)&ctx[((size_t)(b * SDIM) + row) * DD + col]     = make_float2(v0, v1);
        *(float2*)&ctx[((size_t)(b * SDIM) + row + 8) * DD + col] = make_float2(v2, v3);
    }
}

// ---------------------------------------------------------------------------
extern "C" void kernel_launch(void* const* d_in, const int* in_sizes, int n_in,
                              void* d_out, int out_size)
{
    const float* query = (const float*)d_in[0];
    const float* key   = (const float*)d_in[1];
    const float* value = (const float*)d_in[2];
    const float* wq    = (const float*)d_in[4];
    const float* wk    = (const float*)d_in[5];
    const float* wv    = (const float*)d_in[6];
    const float* wo    = (const float*)d_in[7];

    float* out  = (float*)d_out;
    float* attn = out + (size_t)BB * SDIM * DD;

    float *q, *k, *v, *ctx;
    cudaGetSymbolAddress((void**)&q,   g_q);
    cudaGetSymbolAddress((void**)&k,   g_k);
    cudaGetSymbolAddress((void**)&v,   g_v);
    cudaGetSymbolAddress((void**)&ctx, g_ctx);

    const dim3 blk128(128);
    const dim3 blk256(256);
    const dim3 gproj(DD / 128, (BB * SDIM) / 128);       // (8, 32)
    const dim3 gsc(SDIM / 128, SDIM / 128, BB * HH);     // (16, 16, 32)
    const dim3 gctx(1, SDIM / 128, BB * HH);             // (1, 16, 32)

    // Projections: cvt both operands, pre-round outputs to tf32.
    gemm_tf32_nn<true, true, true><<<gproj, blk128>>>(query, wq, q, BB * SDIM, DD, DD);
    gemm_tf32_nn<true, true, true><<<gproj, blk128>>>(key,   wk, k, BB * SDIM, DD, DD);
    gemm_tf32_nn<true, true, true><<<gproj, blk128>>>(value, wv, v, BB * SDIM, DD, DD);

    scores_tf32<<<gsc, blk128>>>(q, k, attn);
    softmax_kernel<<<BB * HH * SDIM, blk256>>>(attn);
    context_tf32<<<gctx, blk256>>>(attn, v, ctx);

    // Out projection: ctx already tf32 (CA=false), exact fp32 output (RO=false).
    gemm_tf32_nn<false, true, false><<<gproj, blk128>>>(ctx, wo, out, BB * SDIM, DD, DD);
}

// round 12
// speedup vs baseline: 1.3116x; 1.3116x over previous
#include <cuda_runtime.h>
#include <cuda_fp16.h>

// Problem constants
#define BB   2
#define SDIM 2048
#define DD   1024
#define HH   16
#define DKK  64

// Scratch (device globals; no allocations allowed). Half2-word storage.
__device__ unsigned g_q[BB * SDIM * DD / 2];
__device__ unsigned g_k[BB * SDIM * DD / 2];
__device__ unsigned g_v[BB * SDIM * DD / 2];
__device__ unsigned g_ctx[BB * SDIM * DD / 2];

// ---------------------------------------------------------------------------
// FP16 helpers
// ---------------------------------------------------------------------------
__device__ __forceinline__ unsigned ph2(float a, float b) {
    __half2 h = __floats2half2_rn(a, b);
    return *reinterpret_cast<unsigned*>(&h);
}

__device__ __forceinline__ void mma_h(float* c,
                                      unsigned a0, unsigned a1, unsigned a2, unsigned a3,
                                      unsigned b0, unsigned b1) {
    asm volatile(
        "mma.sync.aligned.m16n8k16.row.col.f32.f16.f16.f32 "
        "{%0,%1,%2,%3}, {%4,%5,%6,%7}, {%8,%9}, {%0,%1,%2,%3};"
        : "+f"(c[0]), "+f"(c[1]), "+f"(c[2]), "+f"(c[3])
        : "r"(a0), "r"(a1), "r"(a2), "r"(a3), "r"(b0), "r"(b1));
}

// ---------------------------------------------------------------------------
// Shared layouts, indexed by kp = half2-pair index (word = halfs 2kp, 2kp+1).
//
// QUAD (A-operands & scores-B): word(m,kp) = row(kp)*RSTR + mwp(m) + kh(kp)
//   row(kp) = (kp&3) + ((kp>>3)<<2), kh = (kp>>2)&1
//   LDS.128 at row*RSTR + m16*2 + g*4 = {(m0+g,kp),(m0+g,kp+4),(m0+8+g,kp),(m0+8+g,kp+4)}
//   = mma frags {a0, a2, a1, a3}.
// PAIR (gemm/context B): word = row(kp)*PSTR + bsw(n, kh)
// ---------------------------------------------------------------------------
#define RSTR  264
#define PSTR  264
#define PSTRC 136

__device__ __forceinline__ int mwp(int m) {
    return ((m >> 4) << 5) + ((m & 7) << 2) + (((m >> 3) & 1) << 1);
}

// Store 8 words w[0..7] = kps kp0..kp0+7 (kp0 multiple of 8 mod 16-group) for row m.
template <int STRIDE>
__device__ __forceinline__ void store_w8(unsigned* S, int kp0, int m, const unsigned* w) {
    unsigned* b = S + ((kp0 >> 3) << 2) * STRIDE + mwp(m);
    *(uint2*)(b + 0 * STRIDE) = make_uint2(w[0], w[4]);
    *(uint2*)(b + 1 * STRIDE) = make_uint2(w[1], w[5]);
    *(uint2*)(b + 2 * STRIDE) = make_uint2(w[2], w[6]);
    *(uint2*)(b + 3 * STRIDE) = make_uint2(w[3], w[7]);
}

__device__ __forceinline__ int bsw(int n, int q) {
    int w = n * 2 + q;
    w ^= ((w >> 5) & 7) << 1;
    return w;
}

// ---------------------------------------------------------------------------
// FP16 GEMM NN: C[M,N] = A[M,K] * B[K,N]. BM=BN=128, BK=32 (16 kp),
// double-buffered. 256 threads, 8 warps 4m x 2n, warp tile 32x64.
// AH: A is half2 words (no cvt). OH: C stored as half2 words; else fp32.
// ---------------------------------------------------------------------------
template <bool AH, bool OH>
__global__ __launch_bounds__(256, 2)
void gemm_h(const void* __restrict__ Av, const float* __restrict__ B,
            void* __restrict__ Cv, int M, int N, int K)
{
    __shared__ unsigned As[2][8 * RSTR];
    __shared__ unsigned Bs[2][8 * PSTR];

    const int tid  = threadIdx.x;
    const int lane = tid & 31;
    const int warp = tid >> 5;
    const int g    = lane >> 2;
    const int tg   = lane & 3;
    const int wm   = (warp >> 1) * 32;
    const int wn   = (warp & 1) * 64;

    const int am   = tid >> 1;
    const int akp0 = (tid & 1) << 3;          // 0 or 8
    const int bkp  = tid >> 4;                // 0..15
    const int bn   = (tid & 15) << 3;
    const int brow = (bkp & 3) + ((bkp >> 3) << 2);
    const int bq   = (bkp >> 2) & 1;

    const float*    Af = (const float*)Av;
    const unsigned* Ah = (const unsigned*)Av;
    const int Kw = K >> 1;

    unsigned wa[8], wb[8];

    // ---- loaders (into wa / wb) ----
    // A: row am, 16 halfs starting at half index it*32 + (tid&1)*16.
    // B: rows 2bkp, 2bkp+1 of this K-chunk, cols bx*128+bn .. +8.
    float c[16][4];
    #pragma unroll
    for (int i = 0; i < 16; ++i)
        #pragma unroll
        for (int j = 0; j < 4; ++j) c[i][j] = 0.f;

    const int mrow = blockIdx.y * 128 + am;
    const int ncol = blockIdx.x * 128 + bn;

    // prologue: load + stage buffer 0
    {
        if (AH) {
            const unsigned* p = Ah + (size_t)mrow * Kw + akp0;
            *(uint4*)&wa[0] = *(const uint4*)p;
            *(uint4*)&wa[4] = *(const uint4*)(p + 4);
        } else {
            const float* p = Af + (size_t)mrow * K + (akp0 << 1);
            float4 f0 = *(const float4*)p;
            float4 f1 = *(const float4*)(p + 4);
            float4 f2 = *(const float4*)(p + 8);
            float4 f3 = *(const float4*)(p + 12);
            wa[0] = ph2(f0.x, f0.y); wa[1] = ph2(f0.z, f0.w);
            wa[2] = ph2(f1.x, f1.y); wa[3] = ph2(f1.z, f1.w);
            wa[4] = ph2(f2.x, f2.y); wa[5] = ph2(f2.z, f2.w);
            wa[6] = ph2(f3.x, f3.y); wa[7] = ph2(f3.z, f3.w);
        }
        const float* p0 = B + (size_t)(2 * bkp) * N + ncol;
        float4 r00 = *(const float4*)p0;
        float4 r01 = *(const float4*)(p0 + 4);
        float4 r10 = *(const float4*)(p0 + N);
        float4 r11 = *(const float4*)(p0 + N + 4);
        wb[0] = ph2(r00.x, r10.x); wb[1] = ph2(r00.y, r10.y);
        wb[2] = ph2(r00.z, r10.z); wb[3] = ph2(r00.w, r10.w);
        wb[4] = ph2(r01.x, r11.x); wb[5] = ph2(r01.y, r11.y);
        wb[6] = ph2(r01.z, r11.z); wb[7] = ph2(r01.w, r11.w);

        store_w8<RSTR>(As[0], akp0, am, wa);
        unsigned* bb = Bs[0] + brow * PSTR;
        #pragma unroll
        for (int j = 0; j < 8; ++j) bb[bsw(bn + j, bq)] = wb[j];
    }
    __syncthreads();

    const int iters = K >> 5;
    for (int it = 0; it < iters; ++it) {
        const int cur = it & 1;
        const bool more = (it + 1 < iters);

        if (more) {
            if (AH) {
                const unsigned* p = Ah + (size_t)mrow * Kw + (it + 1) * 16 + akp0;
                *(uint4*)&wa[0] = *(const uint4*)p;
                *(uint4*)&wa[4] = *(const uint4*)(p + 4);
            } else {
                const float* p = Af + (size_t)mrow * K + (it + 1) * 32 + (akp0 << 1);
                float4 f0 = *(const float4*)p;
                float4 f1 = *(const float4*)(p + 4);
                float4 f2 = *(const float4*)(p + 8);
                float4 f3 = *(const float4*)(p + 12);
                wa[0] = ph2(f0.x, f0.y); wa[1] = ph2(f0.z, f0.w);
                wa[2] = ph2(f1.x, f1.y); wa[3] = ph2(f1.z, f1.w);
                wa[4] = ph2(f2.x, f2.y); wa[5] = ph2(f2.z, f2.w);
                wa[6] = ph2(f3.x, f3.y); wa[7] = ph2(f3.z, f3.w);
            }
            const float* p0 = B + (size_t)((it + 1) * 32 + 2 * bkp) * N + ncol;
            float4 r00 = *(const float4*)p0;
            float4 r01 = *(const float4*)(p0 + 4);
            float4 r10 = *(const float4*)(p0 + N);
            float4 r11 = *(const float4*)(p0 + N + 4);
            wb[0] = ph2(r00.x, r10.x); wb[1] = ph2(r00.y, r10.y);
            wb[2] = ph2(r00.z, r10.z); wb[3] = ph2(r00.w, r10.w);
            wb[4] = ph2(r01.x, r11.x); wb[5] = ph2(r01.y, r11.y);
            wb[6] = ph2(r01.z, r11.z); wb[7] = ph2(r01.w, r11.w);
        }

        #pragma unroll
        for (int s = 0; s < 2; ++s) {
            const unsigned* Ar = As[cur] + (s * 4 + tg) * RSTR + (g << 2);
            const unsigned* Br = Bs[cur] + (s * 4 + tg) * PSTR;
            uint4 A0 = *(const uint4*)(Ar + wm * 2);
            uint4 A1 = *(const uint4*)(Ar + (wm + 16) * 2);
            #pragma unroll
            for (int ni = 0; ni < 8; ++ni) {
                int w = (wn + ni * 8 + g) * 2;
                w ^= ((w >> 5) & 7) << 1;
                uint2 bv = *(const uint2*)(Br + w);
                mma_h(c[ni],     A0.x, A0.z, A0.y, A0.w, bv.x, bv.y);
                mma_h(c[8 + ni], A1.x, A1.z, A1.y, A1.w, bv.x, bv.y);
            }
        }

        if (more) {
            store_w8<RSTR>(As[1 - cur], akp0, am, wa);
            unsigned* bb = Bs[1 - cur] + brow * PSTR;
            #pragma unroll
            for (int j = 0; j < 8; ++j) bb[bsw(bn + j, bq)] = wb[j];
            __syncthreads();
        }
    }

    #pragma unroll
    for (int mi = 0; mi < 2; ++mi) {
        #pragma unroll
        for (int ni = 0; ni < 8; ++ni) {
            const float* cc = c[mi * 8 + ni];
            const int row = blockIdx.y * 128 + wm + mi * 16 + g;
            const int col = blockIdx.x * 128 + wn + ni * 8 + 2 * tg;
            if (OH) {
                unsigned* C2 = (unsigned*)Cv;
                C2[(size_t)row * (N >> 1) + (col >> 1)]       = ph2(cc[0], cc[1]);
                C2[(size_t)(row + 8) * (N >> 1) + (col >> 1)] = ph2(cc[2], cc[3]);
            } else {
                float* Cf = (float*)Cv;
                *(float2*)&Cf[(size_t)row * N + col]       = make_float2(cc[0], cc[1]);
                *(float2*)&Cf[(size_t)(row + 8) * N + col] = make_float2(cc[2], cc[3]);
            }
        }
    }
}

// ---------------------------------------------------------------------------
// scores: attn[b,h,i,j] = (q.k)/8, causal mask by index, masked = -1e9.
// q,k are half2 words. Single stage: full DK=64 (32 kp) resident.
// 256 threads, 8 warps 4m x 2n, warp tile 32x64, both operands QUAD.
// ---------------------------------------------------------------------------
__global__ __launch_bounds__(256, 2)
void scores_h(const unsigned* __restrict__ q2, const unsigned* __restrict__ k2,
              float* __restrict__ attn)
{
    const int bx = blockIdx.x;
    const int by = blockIdx.y;
    if (bx > by) return;
    const int z = blockIdx.z;
    const int b = z >> 4;
    const int h = z & 15;

    __shared__ unsigned As[16 * RSTR];
    __shared__ unsigned Bs[16 * RSTR];

    const int tid  = threadIdx.x;
    const int lane = tid & 31;
    const int warp = tid >> 5;
    const int g    = lane >> 2;
    const int tg   = lane & 3;
    const int wm   = (warp >> 1) * 32;
    const int wn   = (warp & 1) * 64;

    const int r   = tid >> 1;
    const int kp0 = (tid & 1) << 4;   // 0 or 16

    const unsigned* qp = q2 + (size_t)(b * SDIM + by * 128 + r) * (DD / 2) + h * 32 + kp0;
    const unsigned* kp = k2 + (size_t)(b * SDIM + bx * 128 + r) * (DD / 2) + h * 32 + kp0;

    unsigned w[16];
    *(uint4*)&w[0]  = *(const uint4*)qp;
    *(uint4*)&w[4]  = *(const uint4*)(qp + 4);
    *(uint4*)&w[8]  = *(const uint4*)(qp + 8);
    *(uint4*)&w[12] = *(const uint4*)(qp + 12);
    store_w8<RSTR>(As, kp0,     r, w);
    store_w8<RSTR>(As, kp0 + 8, r, w + 8);
    *(uint4*)&w[0]  = *(const uint4*)kp;
    *(uint4*)&w[4]  = *(const uint4*)(kp + 4);
    *(uint4*)&w[8]  = *(const uint4*)(kp + 8);
    *(uint4*)&w[12] = *(const uint4*)(kp + 12);
    store_w8<RSTR>(Bs, kp0,     r, w);
    store_w8<RSTR>(Bs, kp0 + 8, r, w + 8);

    float c[16][4];
    #pragma unroll
    for (int i = 0; i < 16; ++i)
        #pragma unroll
        for (int j = 0; j < 4; ++j) c[i][j] = 0.f;

    __syncthreads();

    #pragma unroll
    for (int s = 0; s < 4; ++s) {
        const unsigned* Ar = As + (s * 4 + tg) * RSTR + (g << 2);
        const unsigned* Br = Bs + (s * 4 + tg) * RSTR + (g << 2);
        uint4 A0 = *(const uint4*)(Ar + wm * 2);
        uint4 A1 = *(const uint4*)(Ar + (wm + 16) * 2);
        #pragma unroll
        for (int np = 0; np < 4; ++np) {
            uint4 Bv = *(const uint4*)(Br + (wn + np * 16) * 2);
            const int ni = np * 2;
            mma_h(c[ni],         A0.x, A0.z, A0.y, A0.w, Bv.x, Bv.y);
            mma_h(c[ni + 1],     A0.x, A0.z, A0.y, A0.w, Bv.z, Bv.w);
            mma_h(c[8 + ni],     A1.x, A1.z, A1.y, A1.w, Bv.x, Bv.y);
            mma_h(c[8 + ni + 1], A1.x, A1.z, A1.y, A1.w, Bv.z, Bv.w);
        }
    }

    #pragma unroll
    for (int mi = 0; mi < 2; ++mi) {
        #pragma unroll
        for (int ni = 0; ni < 8; ++ni) {
            const float* cc = c[mi * 8 + ni];
            const int i0 = by * 128 + wm + mi * 16 + g;
            const int j0 = bx * 128 + wn + ni * 8 + 2 * tg;
            #pragma unroll
            for (int rr = 0; rr < 2; ++rr) {
                const int i = i0 + rr * 8;
                float2 o;
                o.x = (j0     > i) ? -1e9f : cc[rr * 2 + 0] * 0.125f;
                o.y = (j0 + 1 > i) ? -1e9f : cc[rr * 2 + 1] * 0.125f;
                *(float2*)&attn[((size_t)z * SDIM + i) * SDIM + j0] = o;
            }
        }
    }
}

// ---------------------------------------------------------------------------
// Row softmax in place over computed prefix [0, L); zero-fill [L, S).
// ---------------------------------------------------------------------------
__global__ __launch_bounds__(256)
void softmax_kernel(float* __restrict__ attn)
{
    __shared__ float redmax[8];
    __shared__ float redsum[8];

    const int r   = blockIdx.x;
    const int i   = r & (SDIM - 1);
    const int L   = ((i >> 7) + 1) << 7;
    const int tid = threadIdx.x;
    float* row = attn + (size_t)r * SDIM;

    float x[8];
    float m = -3.4e38f;
    #pragma unroll
    for (int t = 0; t < 8; ++t) {
        const int j = tid + t * 256;
        if (j < L) { x[t] = row[j]; m = fmaxf(m, x[t]); }
    }
    #pragma unroll
    for (int o = 16; o; o >>= 1) m = fmaxf(m, __shfl_xor_sync(0xffffffffu, m, o));
    if ((tid & 31) == 0) redmax[tid >> 5] = m;
    __syncthreads();
    if (tid == 0) {
        float t = redmax[0];
        #pragma unroll
        for (int w = 1; w < 8; ++w) t = fmaxf(t, redmax[w]);
        redmax[0] = t;
    }
    __syncthreads();
    const float M = redmax[0];

    float s = 0.f;
    #pragma unroll
    for (int t = 0; t < 8; ++t) {
        const int j = tid + t * 256;
        if (j < L) { x[t] = __expf(x[t] - M); s += x[t]; }
    }
    #pragma unroll
    for (int o = 16; o; o >>= 1) s += __shfl_xor_sync(0xffffffffu, s, o);
    if ((tid & 31) == 0) redsum[tid >> 5] = s;
    __syncthreads();
    if (tid == 0) {
        float t = 0.f;
        #pragma unroll
        for (int w = 0; w < 8; ++w) t += redsum[w];
        redsum[0] = t;
    }
    __syncthreads();
    const float inv = 1.f / redsum[0];

    #pragma unroll
    for (int t = 0; t < 8; ++t) {
        const int j = tid + t * 256;
        if (j < L) row[j] = x[t] * inv;
    }
    for (int j = L + tid; j < SDIM; j += 256) row[j] = 0.f;
}

// ---------------------------------------------------------------------------
// context: ctx[b,i,h*64+c] = sum_j attn[z,i,j] * v[b,j,h*64+c]
// attn fp32 -> cvt half; v half2 (cross-row repacked). ctx stored half2.
// 256 threads, 8 warps m-stacked, warp tile 16x64, BK=32, double-buffered.
// ---------------------------------------------------------------------------
__global__ __launch_bounds__(256, 2)
void context_h(const float* __restrict__ attn, const unsigned* __restrict__ v2,
               unsigned* __restrict__ ctx2)
{
    const int z = blockIdx.z;
    const int b = z >> 4;
    const int h = z & 15;
    const int i0 = blockIdx.y * 128;

    __shared__ unsigned As[2][8 * RSTR];
    __shared__ unsigned Bs[2][8 * PSTRC];

    const int tid  = threadIdx.x;
    const int lane = tid & 31;
    const int warp = tid >> 5;
    const int g    = lane >> 2;
    const int tg   = lane & 3;

    const int am   = tid >> 1;
    const int akp0 = (tid & 1) << 3;
    const int bkp  = tid >> 4;
    const int bc   = (tid & 15) << 2;
    const int brow = (bkp & 3) + ((bkp >> 3) << 2);
    const int bq   = (bkp >> 2) & 1;

    unsigned wa[8], wb[4];

    float c[8][4];
    #pragma unroll
    for (int i = 0; i < 8; ++i)
        #pragma unroll
        for (int j = 0; j < 4; ++j) c[i][j] = 0.f;

    const float* Ab = attn + ((size_t)z * SDIM + i0 + am) * SDIM + (akp0 << 1);
    const __half* vb = (const __half*)v2;

    // prologue
    {
        float4 f0 = *(const float4*)Ab;
        float4 f1 = *(const float4*)(Ab + 4);
        float4 f2 = *(const float4*)(Ab + 8);
        float4 f3 = *(const float4*)(Ab + 12);
        wa[0] = ph2(f0.x, f0.y); wa[1] = ph2(f0.z, f0.w);
        wa[2] = ph2(f1.x, f1.y); wa[3] = ph2(f1.z, f1.w);
        wa[4] = ph2(f2.x, f2.y); wa[5] = ph2(f2.z, f2.w);
        wa[6] = ph2(f3.x, f3.y); wa[7] = ph2(f3.z, f3.w);
        const __half* r0 = vb + (size_t)(b * SDIM + 2 * bkp) * DD + h * DKK + bc;
        uint2 u0 = *(const uint2*)r0;
        uint2 u1 = *(const uint2*)(r0 + DD);
        const __half* h0 = (const __half*)&u0;
        const __half* h1 = (const __half*)&u1;
        #pragma unroll
        for (int j = 0; j < 4; ++j) {
            __half2 hh = __halves2half2(h0[j], h1[j]);
            wb[j] = *(unsigned*)&hh;
        }
        store_w8<RSTR>(As[0], akp0, am, wa);
        unsigned* bb = Bs[0] + brow * PSTRC;
        #pragma unroll
        for (int j = 0; j < 4; ++j) bb[bsw(bc + j, bq)] = wb[j];
    }
    __syncthreads();

    const int iters = (i0 + 128) >> 5;
    for (int it = 0; it < iters; ++it) {
        const int cur = it & 1;
        const bool more = (it + 1 < iters);

        if (more) {
            const float* p = Ab + (it + 1) * 32;
            float4 f0 = *(const float4*)p;
            float4 f1 = *(const float4*)(p + 4);
            float4 f2 = *(const float4*)(p + 8);
            float4 f3 = *(const float4*)(p + 12);
            wa[0] = ph2(f0.x, f0.y); wa[1] = ph2(f0.z, f0.w);
            wa[2] = ph2(f1.x, f1.y); wa[3] = ph2(f1.z, f1.w);
            wa[4] = ph2(f2.x, f2.y); wa[5] = ph2(f2.z, f2.w);
            wa[6] = ph2(f3.x, f3.y); wa[7] = ph2(f3.z, f3.w);
            const __half* r0 = vb + (size_t)(b * SDIM + (it + 1) * 32 + 2 * bkp) * DD + h * DKK + bc;
            uint2 u0 = *(const uint2*)r0;
            uint2 u1 = *(const uint2*)(r0 + DD);
            const __half* h0 = (const __half*)&u0;
            const __half* h1 = (const __half*)&u1;
            #pragma unroll
            for (int j = 0; j < 4; ++j) {
                __half2 hh = __halves2half2(h0[j], h1[j]);
                wb[j] = *(unsigned*)&hh;
            }
        }

        #pragma unroll
        for (int s = 0; s < 2; ++s) {
            const unsigned* Ar = As[cur] + (s * 4 + tg) * RSTR + (g << 2);
            const unsigned* Br = Bs[cur] + (s * 4 + tg) * PSTRC;
            uint4 A0 = *(const uint4*)(Ar + warp * 32);
            #pragma unroll
            for (int ni = 0; ni < 8; ++ni) {
                int w = (ni * 8 + g) * 2;
                w ^= ((w >> 5) & 7) << 1;
                uint2 bv = *(const uint2*)(Br + w);
                mma_h(c[ni], A0.x, A0.z, A0.y, A0.w, bv.x, bv.y);
            }
        }

        if (more) {
            store_w8<RSTR>(As[1 - cur], akp0, am, wa);
            unsigned* bb = Bs[1 - cur] + brow * PSTRC;
            #pragma unroll
            for (int j = 0; j < 4; ++j) bb[bsw(bc + j, bq)] = wb[j];
            __syncthreads();
        }
    }

    #pragma unroll
    for (int ni = 0; ni < 8; ++ni) {
        const int row = i0 + warp * 16 + g;
        const int wcol = h * 32 + ni * 4 + tg;   // half2-word column
        ctx2[(size_t)(b * SDIM + row) * (DD / 2) + wcol]     = ph2(c[ni][0], c[ni][1]);
        ctx2[(size_t)(b * SDIM + row + 8) * (DD / 2) + wcol] = ph2(c[ni][2], c[ni][3]);
    }
}

// ---------------------------------------------------------------------------
extern "C" void kernel_launch(void* const* d_in, const int* in_sizes, int n_in,
                              void* d_out, int out_size)
{
    const float* query = (const float*)d_in[0];
    const float* key   = (const float*)d_in[1];
    const float* value = (const float*)d_in[2];
    const float* wq    = (const float*)d_in[4];
    const float* wk    = (const float*)d_in[5];
    const float* wv    = (const float*)d_in[6];
    const float* wo    = (const float*)d_in[7];

    float* out  = (float*)d_out;
    float* attn = out + (size_t)BB * SDIM * DD;

    unsigned *q, *k, *v, *ctx;
    cudaGetSymbolAddress((void**)&q,   g_q);
    cudaGetSymbolAddress((void**)&k,   g_k);
    cudaGetSymbolAddress((void**)&v,   g_v);
    cudaGetSymbolAddress((void**)&ctx, g_ctx);

    const dim3 blk(256);
    const dim3 gproj(DD / 128, (BB * SDIM) / 128);       // (8, 32)
    const dim3 gsc(SDIM / 128, SDIM / 128, BB * HH);     // (16, 16, 32)
    const dim3 gctx(1, SDIM / 128, BB * HH);             // (1, 16, 32)

    // Projections: fp32 A cvt'd to fp16, outputs stored as fp16.
    gemm_h<false, true><<<gproj, blk>>>(query, wq, q, BB * SDIM, DD, DD);
    gemm_h<false, true><<<gproj, blk>>>(key,   wk, k, BB * SDIM, DD, DD);
    gemm_h<false, true><<<gproj, blk>>>(value, wv, v, BB * SDIM, DD, DD);

    scores_h<<<gsc, blk>>>(q, k, attn);
    softmax_kernel<<<BB * HH * SDIM, blk>>>(attn);
    context_h<<<gctx, blk>>>(attn, v, ctx);

    // Out projection: A is fp16 ctx, exact fp32 output.
    gemm_h<true, false><<<gproj, blk>>>(ctx, wo, out, BB * SDIM, DD, DD);
}

// round 13
// speedup vs baseline: 1.7200x; 1.3114x over previous
#include <cuda_runtime.h>
#include <cuda_fp16.h>

// Problem constants
#define BB   2
#define SDIM 2048
#define DD   1024
#define HH   16
#define DKK  64

// Scratch (device globals; no allocations allowed).
__device__ unsigned g_q[BB * SDIM * DD / 2];
__device__ unsigned g_k[BB * SDIM * DD / 2];
__device__ unsigned g_v[BB * SDIM * DD / 2];
__device__ unsigned g_ctx[BB * SDIM * DD / 2];
__device__ unsigned g_e[(size_t)BB * HH * SDIM * SDIM / 2];  // unnormalized exp, fp16
__device__ float    g_rowsum[BB * HH * SDIM];

// ---------------------------------------------------------------------------
// FP16 helpers
// ---------------------------------------------------------------------------
__device__ __forceinline__ unsigned ph2(float a, float b) {
    __half2 h = __floats2half2_rn(a, b);
    return *reinterpret_cast<unsigned*>(&h);
}

__device__ __forceinline__ void mma_h(float* c,
                                      unsigned a0, unsigned a1, unsigned a2, unsigned a3,
                                      unsigned b0, unsigned b1) {
    asm volatile(
        "mma.sync.aligned.m16n8k16.row.col.f32.f16.f16.f32 "
        "{%0,%1,%2,%3}, {%4,%5,%6,%7}, {%8,%9}, {%0,%1,%2,%3};"
        : "+f"(c[0]), "+f"(c[1]), "+f"(c[2]), "+f"(c[3])
        : "r"(a0), "r"(a1), "r"(a2), "r"(a3), "r"(b0), "r"(b1));
}

// ---------------------------------------------------------------------------
// Shared layouts, indexed by kp = half2-pair index (word = halfs 2kp, 2kp+1).
// QUAD: word(m,kp) = row(kp)*RSTR + mwp(m) + kh(kp); LDS.128 = full A frag.
// PAIR (B of NN gemm / V): word = row(kp)*PSTR + bsw(n, kh)
// ---------------------------------------------------------------------------
#define RSTR  264
#define PSTR  264
#define PSTRC 136

__device__ __forceinline__ int mwp(int m) {
    return ((m >> 4) << 5) + ((m & 7) << 2) + (((m >> 3) & 1) << 1);
}

template <int STRIDE>
__device__ __forceinline__ void store_w8(unsigned* S, int kp0, int m, const unsigned* w) {
    unsigned* b = S + ((kp0 >> 3) << 2) * STRIDE + mwp(m);
    *(uint2*)(b + 0 * STRIDE) = make_uint2(w[0], w[4]);
    *(uint2*)(b + 1 * STRIDE) = make_uint2(w[1], w[5]);
    *(uint2*)(b + 2 * STRIDE) = make_uint2(w[2], w[6]);
    *(uint2*)(b + 3 * STRIDE) = make_uint2(w[3], w[7]);
}

__device__ __forceinline__ int bsw(int n, int q) {
    int w = n * 2 + q;
    w ^= ((w >> 5) & 7) << 1;
    return w;
}

// ---------------------------------------------------------------------------
// Combined QKV projection: one launch; n-tile block selects (A, W, C) triple.
// Body identical to the verified fp16 GEMM (A fp32 cvt'd, C fp16).
// Grid (24, 32): blockIdx.x>>3 selects projection, &7 is the n tile.
// ---------------------------------------------------------------------------
__global__ __launch_bounds__(256, 2)
void qkv_h(const float* __restrict__ Aq, const float* __restrict__ Ak,
           const float* __restrict__ Avl,
           const float* __restrict__ Wq, const float* __restrict__ Wk,
           const float* __restrict__ Wv,
           unsigned* __restrict__ Cq, unsigned* __restrict__ Ck,
           unsigned* __restrict__ Cv)
{
    const int sel = blockIdx.x >> 3;
    const int bxl = blockIdx.x & 7;
    const float* Af = (sel == 0) ? Aq : (sel == 1) ? Ak : Avl;
    const float* B  = (sel == 0) ? Wq : (sel == 1) ? Wk : Wv;
    unsigned* C2    = (sel == 0) ? Cq : (sel == 1) ? Ck : Cv;
    const int N = DD, K = DD;

    __shared__ unsigned As[2][8 * RSTR];
    __shared__ unsigned Bs[2][8 * PSTR];

    const int tid  = threadIdx.x;
    const int lane = tid & 31;
    const int warp = tid >> 5;
    const int g    = lane >> 2;
    const int tg   = lane & 3;
    const int wm   = (warp >> 1) * 32;
    const int wn   = (warp & 1) * 64;

    const int am   = tid >> 1;
    const int akp0 = (tid & 1) << 3;
    const int bkp  = tid >> 4;
    const int bn   = (tid & 15) << 3;
    const int brow = (bkp & 3) + ((bkp >> 3) << 2);
    const int bq   = (bkp >> 2) & 1;

    unsigned wa[8], wb[8];
    float c[16][4];
    #pragma unroll
    for (int i = 0; i < 16; ++i)
        #pragma unroll
        for (int j = 0; j < 4; ++j) c[i][j] = 0.f;

    const int mrow = blockIdx.y * 128 + am;
    const int ncol = bxl * 128 + bn;

    {
        const float* p = Af + (size_t)mrow * K + (akp0 << 1);
        float4 f0 = *(const float4*)p;
        float4 f1 = *(const float4*)(p + 4);
        float4 f2 = *(const float4*)(p + 8);
        float4 f3 = *(const float4*)(p + 12);
        wa[0] = ph2(f0.x, f0.y); wa[1] = ph2(f0.z, f0.w);
        wa[2] = ph2(f1.x, f1.y); wa[3] = ph2(f1.z, f1.w);
        wa[4] = ph2(f2.x, f2.y); wa[5] = ph2(f2.z, f2.w);
        wa[6] = ph2(f3.x, f3.y); wa[7] = ph2(f3.z, f3.w);
        const float* p0 = B + (size_t)(2 * bkp) * N + ncol;
        float4 r00 = *(const float4*)p0;
        float4 r01 = *(const float4*)(p0 + 4);
        float4 r10 = *(const float4*)(p0 + N);
        float4 r11 = *(const float4*)(p0 + N + 4);
        wb[0] = ph2(r00.x, r10.x); wb[1] = ph2(r00.y, r10.y);
        wb[2] = ph2(r00.z, r10.z); wb[3] = ph2(r00.w, r10.w);
        wb[4] = ph2(r01.x, r11.x); wb[5] = ph2(r01.y, r11.y);
        wb[6] = ph2(r01.z, r11.z); wb[7] = ph2(r01.w, r11.w);
        store_w8<RSTR>(As[0], akp0, am, wa);
        unsigned* bb = Bs[0] + brow * PSTR;
        #pragma unroll
        for (int j = 0; j < 8; ++j) bb[bsw(bn + j, bq)] = wb[j];
    }
    __syncthreads();

    const int iters = K >> 5;
    for (int it = 0; it < iters; ++it) {
        const int cur = it & 1;
        const bool more = (it + 1 < iters);
        if (more) {
            const float* p = Af + (size_t)mrow * K + (it + 1) * 32 + (akp0 << 1);
            float4 f0 = *(const float4*)p;
            float4 f1 = *(const float4*)(p + 4);
            float4 f2 = *(const float4*)(p + 8);
            float4 f3 = *(const float4*)(p + 12);
            wa[0] = ph2(f0.x, f0.y); wa[1] = ph2(f0.z, f0.w);
            wa[2] = ph2(f1.x, f1.y); wa[3] = ph2(f1.z, f1.w);
            wa[4] = ph2(f2.x, f2.y); wa[5] = ph2(f2.z, f2.w);
            wa[6] = ph2(f3.x, f3.y); wa[7] = ph2(f3.z, f3.w);
            const float* p0 = B + (size_t)((it + 1) * 32 + 2 * bkp) * N + ncol;
            float4 r00 = *(const float4*)p0;
            float4 r01 = *(const float4*)(p0 + 4);
            float4 r10 = *(const float4*)(p0 + N);
            float4 r11 = *(const float4*)(p0 + N + 4);
            wb[0] = ph2(r00.x, r10.x); wb[1] = ph2(r00.y, r10.y);
            wb[2] = ph2(r00.z, r10.z); wb[3] = ph2(r00.w, r10.w);
            wb[4] = ph2(r01.x, r11.x); wb[5] = ph2(r01.y, r11.y);
            wb[6] = ph2(r01.z, r11.z); wb[7] = ph2(r01.w, r11.w);
        }

        #pragma unroll
        for (int s = 0; s < 2; ++s) {
            const unsigned* Ar = As[cur] + (s * 4 + tg) * RSTR + (g << 2);
            const unsigned* Br = Bs[cur] + (s * 4 + tg) * PSTR;
            uint4 A0 = *(const uint4*)(Ar + wm * 2);
            uint4 A1 = *(const uint4*)(Ar + (wm + 16) * 2);
            #pragma unroll
            for (int ni = 0; ni < 8; ++ni) {
                int w = (wn + ni * 8 + g) * 2;
                w ^= ((w >> 5) & 7) << 1;
                uint2 bv = *(const uint2*)(Br + w);
                mma_h(c[ni],     A0.x, A0.z, A0.y, A0.w, bv.x, bv.y);
                mma_h(c[8 + ni], A1.x, A1.z, A1.y, A1.w, bv.x, bv.y);
            }
        }

        if (more) {
            store_w8<RSTR>(As[1 - cur], akp0, am, wa);
            unsigned* bb = Bs[1 - cur] + brow * PSTR;
            #pragma unroll
            for (int j = 0; j < 8; ++j) bb[bsw(bn + j, bq)] = wb[j];
            __syncthreads();
        }
    }

    #pragma unroll
    for (int mi = 0; mi < 2; ++mi) {
        #pragma unroll
        for (int ni = 0; ni < 8; ++ni) {
            const float* cc = c[mi * 8 + ni];
            const int row = blockIdx.y * 128 + wm + mi * 16 + g;
            const int col = bxl * 128 + wn + ni * 8 + 2 * tg;
            C2[(size_t)row * (DD / 2) + (col >> 1)]       = ph2(cc[0], cc[1]);
            C2[(size_t)(row + 8) * (DD / 2) + (col >> 1)] = ph2(cc[2], cc[3]);
        }
    }
}

// ---------------------------------------------------------------------------
// Fused attention: per (query-tile by, z): loop key tiles bx<=by.
//  S = Q·K^T; E = exp(S/8) (masked on diag tile); E -> fp16 scratch + fp16
//  A-frags (in-register) -> O += E·V. ctx = O / rowsum. Deterministic.
// 8 warps m-stacked, warp tile 16 rows x 128 keys, processed in 64-key halves.
// ---------------------------------------------------------------------------
__global__ __launch_bounds__(256)
void fused_attn(const unsigned* __restrict__ q2, const unsigned* __restrict__ k2,
                const unsigned* __restrict__ v2, unsigned* __restrict__ e2,
                float* __restrict__ rowsum, unsigned* __restrict__ ctx2)
{
    const int by = (SDIM / 128 - 1) - blockIdx.x;   // heavy CTAs first
    const int z  = blockIdx.y;
    const int b  = z >> 4;
    const int h  = z & 15;

    __shared__ unsigned Qs[16 * RSTR];
    __shared__ unsigned Ks[16 * RSTR];
    __shared__ unsigned Vs[32 * PSTRC];

    const int tid  = threadIdx.x;
    const int lane = tid & 31;
    const int warp = tid >> 5;
    const int g    = lane >> 2;
    const int tg   = lane & 3;
    const int wm   = warp * 16;

    // Q/K loader coords
    const int r   = tid >> 1;
    const int kp0 = (tid & 1) << 4;
    // V loader coords
    const int vkp  = tid >> 2;                       // 0..63 key pairs
    const int vrow = (vkp & 3) + ((vkp >> 3) << 2);  // 0..31
    const int vq   = (vkp >> 2) & 1;
    const int vc0  = (tid & 3) << 4;                 // 16 head cols

    // Load Q tile once
    {
        const unsigned* qp = q2 + (size_t)(b * SDIM + by * 128 + r) * (DD / 2) + h * 32 + kp0;
        unsigned w[16];
        *(uint4*)&w[0]  = *(const uint4*)qp;
        *(uint4*)&w[4]  = *(const uint4*)(qp + 4);
        *(uint4*)&w[8]  = *(const uint4*)(qp + 8);
        *(uint4*)&w[12] = *(const uint4*)(qp + 12);
        store_w8<RSTR>(Qs, kp0,     r, w);
        store_w8<RSTR>(Qs, kp0 + 8, r, w + 8);
    }

    float co[8][4];
    #pragma unroll
    for (int i = 0; i < 8; ++i)
        #pragma unroll
        for (int j = 0; j < 4; ++j) co[i][j] = 0.f;
    float rs0 = 0.f, rs1 = 0.f;

    const int i0 = by * 128 + wm + g;   // this thread's first row

    for (int bx = 0; bx <= by; ++bx) {
        __syncthreads();   // previous-iter smem reads complete (also orders Q store on it 0)
        // Load K tile
        {
            const unsigned* kp = k2 + (size_t)(b * SDIM + bx * 128 + r) * (DD / 2) + h * 32 + kp0;
            unsigned w[16];
            *(uint4*)&w[0]  = *(const uint4*)kp;
            *(uint4*)&w[4]  = *(const uint4*)(kp + 4);
            *(uint4*)&w[8]  = *(const uint4*)(kp + 8);
            *(uint4*)&w[12] = *(const uint4*)(kp + 12);
            store_w8<RSTR>(Ks, kp0,     r, w);
            store_w8<RSTR>(Ks, kp0 + 8, r, w + 8);
        }
        // Load V tile (cross-key-row half2 repack into PAIR layout)
        {
            const unsigned* vp = v2 + (size_t)(b * SDIM + bx * 128 + 2 * vkp) * (DD / 2)
                                 + h * 32 + (vc0 >> 1);
            unsigned r0[8], r1[8];
            *(uint4*)&r0[0] = *(const uint4*)vp;
            *(uint4*)&r0[4] = *(const uint4*)(vp + 4);
            *(uint4*)&r1[0] = *(const uint4*)(vp + DD / 2);
            *(uint4*)&r1[4] = *(const uint4*)(vp + DD / 2 + 4);
            const __half* h0 = (const __half*)r0;
            const __half* h1 = (const __half*)r1;
            unsigned* bb = Vs + vrow * PSTRC;
            #pragma unroll
            for (int j = 0; j < 16; ++j) {
                __half2 hh = __halves2half2(h0[j], h1[j]);
                bb[bsw(vc0 + j, vq)] = *(unsigned*)&hh;
            }
        }
        __syncthreads();

        const bool diag = (bx == by);
        #pragma unroll
        for (int half = 0; half < 2; ++half) {
            float cs[8][4];
            #pragma unroll
            for (int i = 0; i < 8; ++i)
                #pragma unroll
                for (int j = 0; j < 4; ++j) cs[i][j] = 0.f;

            // S = Q K^T for 64-key half
            #pragma unroll
            for (int s = 0; s < 4; ++s) {
                const unsigned* Ar = Qs + (s * 4 + tg) * RSTR + (g << 2);
                const unsigned* Br = Ks + (s * 4 + tg) * RSTR + (g << 2);
                uint4 A0 = *(const uint4*)(Ar + wm * 2);
                #pragma unroll
                for (int np = 0; np < 4; ++np) {
                    uint4 Bv = *(const uint4*)(Br + (half * 64 + np * 16) * 2);
                    mma_h(cs[2 * np],     A0.x, A0.z, A0.y, A0.w, Bv.x, Bv.y);
                    mma_h(cs[2 * np + 1], A0.x, A0.z, A0.y, A0.w, Bv.z, Bv.w);
                }
            }

            // exp + mask + rowsum + pack E frags + store E (fp16)
            unsigned ea[4][4];
            #pragma unroll
            for (int ni = 0; ni < 8; ++ni) {
                const int j0 = bx * 128 + half * 64 + ni * 8 + 2 * tg;
                float e00 = __expf(cs[ni][0] * 0.125f);
                float e01 = __expf(cs[ni][1] * 0.125f);
                float e10 = __expf(cs[ni][2] * 0.125f);
                float e11 = __expf(cs[ni][3] * 0.125f);
                if (diag) {
                    if (j0     > i0)     e00 = 0.f;
                    if (j0 + 1 > i0)     e01 = 0.f;
                    if (j0     > i0 + 8) e10 = 0.f;
                    if (j0 + 1 > i0 + 8) e11 = 0.f;
                }
                rs0 += e00 + e01;
                rs1 += e10 + e11;
                const unsigned w0 = ph2(e00, e01);
                const unsigned w1 = ph2(e10, e11);
                e2[((size_t)z * SDIM + i0) * (SDIM / 2) + (j0 >> 1)]     = w0;
                e2[((size_t)z * SDIM + i0 + 8) * (SDIM / 2) + (j0 >> 1)] = w1;
                ea[ni >> 1][(ni & 1) * 2 + 0] = w0;
                ea[ni >> 1][(ni & 1) * 2 + 1] = w1;
            }

            // O += E · V  (E frags in registers; V from PAIR layout)
            #pragma unroll
            for (int t = 0; t < 4; ++t) {
                const int kt = half * 4 + t;
                const unsigned* Br = Vs + (kt * 4 + tg) * PSTRC;
                #pragma unroll
                for (int nj = 0; nj < 8; ++nj) {
                    int w = (nj * 8 + g) * 2;
                    w ^= ((w >> 5) & 7) << 1;
                    uint2 bv = *(const uint2*)(Br + w);
                    mma_h(co[nj], ea[t][0], ea[t][1], ea[t][2], ea[t][3], bv.x, bv.y);
                }
            }
        }
    }

    // Row sums: reduce over the 4 tg lanes (each owns disjoint columns)
    rs0 += __shfl_xor_sync(0xffffffffu, rs0, 1);
    rs0 += __shfl_xor_sync(0xffffffffu, rs0, 2);
    rs1 += __shfl_xor_sync(0xffffffffu, rs1, 1);
    rs1 += __shfl_xor_sync(0xffffffffu, rs1, 2);
    if (tg == 0) {
        rowsum[(size_t)z * SDIM + i0]     = rs0;
        rowsum[(size_t)z * SDIM + i0 + 8] = rs1;
    }
    const float inv0 = 1.f / rs0;
    const float inv1 = 1.f / rs1;

    #pragma unroll
    for (int nj = 0; nj < 8; ++nj) {
        const int wcol = h * 32 + nj * 4 + tg;
        ctx2[(size_t)(b * SDIM + i0) * (DD / 2) + wcol]     = ph2(co[nj][0] * inv0, co[nj][1] * inv0);
        ctx2[(size_t)(b * SDIM + i0 + 8) * (DD / 2) + wcol] = ph2(co[nj][2] * inv1, co[nj][3] * inv1);
    }
}

// ---------------------------------------------------------------------------
// Normalize: attn[r][j] = E[r][j] / rowsum[r] (fp16 -> fp32), zero-fill tail.
// ---------------------------------------------------------------------------
__global__ __launch_bounds__(256)
void norm_attn(const unsigned* __restrict__ e2, const float* __restrict__ rowsum,
               float* __restrict__ attn)
{
    const int r   = blockIdx.x;
    const int i   = r & (SDIM - 1);
    const int L   = ((i >> 7) + 1) << 7;
    const int tid = threadIdx.x;
    const float inv = 1.f / rowsum[r];
    const unsigned* erow = e2 + (size_t)r * (SDIM / 2);
    float* orow = attn + (size_t)r * SDIM;

    for (int q = tid; q < (L >> 2); q += 256) {   // q indexes groups of 4 elements
        uint2 ew = *(const uint2*)(erow + q * 2);
        __half2 h0 = *(__half2*)&ew.x;
        __half2 h1 = *(__half2*)&ew.y;
        float2 f0 = __half22float2(h0);
        float2 f1 = __half22float2(h1);
        float4 o = make_float4(f0.x * inv, f0.y * inv, f1.x * inv, f1.y * inv);
        *(float4*)(orow + q * 4) = o;
    }
    const float4 z4 = make_float4(0.f, 0.f, 0.f, 0.f);
    for (int q = (L >> 2) + tid; q < (SDIM >> 2); q += 256)
        *(float4*)(orow + q * 4) = z4;
}

// ---------------------------------------------------------------------------
// Output projection (fp16 A, fp32 C) — verified R12 kernel.
// ---------------------------------------------------------------------------
__global__ __launch_bounds__(256, 2)
void outproj_h(const unsigned* __restrict__ Ah, const float* __restrict__ B,
               float* __restrict__ Cf, int M, int N, int K)
{
    __shared__ unsigned As[2][8 * RSTR];
    __shared__ unsigned Bs[2][8 * PSTR];

    const int tid  = threadIdx.x;
    const int lane = tid & 31;
    const int warp = tid >> 5;
    const int g    = lane >> 2;
    const int tg   = lane & 3;
    const int wm   = (warp >> 1) * 32;
    const int wn   = (warp & 1) * 64;

    const int am   = tid >> 1;
    const int akp0 = (tid & 1) << 3;
    const int bkp  = tid >> 4;
    const int bn   = (tid & 15) << 3;
    const int brow = (bkp & 3) + ((bkp >> 3) << 2);
    const int bq   = (bkp >> 2) & 1;
    const int Kw = K >> 1;

    unsigned wa[8], wb[8];
    float c[16][4];
    #pragma unroll
    for (int i = 0; i < 16; ++i)
        #pragma unroll
        for (int j = 0; j < 4; ++j) c[i][j] = 0.f;

    const int mrow = blockIdx.y * 128 + am;
    const int ncol = blockIdx.x * 128 + bn;

    {
        const unsigned* p = Ah + (size_t)mrow * Kw + akp0;
        *(uint4*)&wa[0] = *(const uint4*)p;
        *(uint4*)&wa[4] = *(const uint4*)(p + 4);
        const float* p0 = B + (size_t)(2 * bkp) * N + ncol;
        float4 r00 = *(const float4*)p0;
        float4 r01 = *(const float4*)(p0 + 4);
        float4 r10 = *(const float4*)(p0 + N);
        float4 r11 = *(const float4*)(p0 + N + 4);
        wb[0] = ph2(r00.x, r10.x); wb[1] = ph2(r00.y, r10.y);
        wb[2] = ph2(r00.z, r10.z); wb[3] = ph2(r00.w, r10.w);
        wb[4] = ph2(r01.x, r11.x); wb[5] = ph2(r01.y, r11.y);
        wb[6] = ph2(r01.z, r11.z); wb[7] = ph2(r01.w, r11.w);
        store_w8<RSTR>(As[0], akp0, am, wa);
        unsigned* bb = Bs[0] + brow * PSTR;
        #pragma unroll
        for (int j = 0; j < 8; ++j) bb[bsw(bn + j, bq)] = wb[j];
    }
    __syncthreads();

    const int iters = K >> 5;
    for (int it = 0; it < iters; ++it) {
        const int cur = it & 1;
        const bool more = (it + 1 < iters);
        if (more) {
            const unsigned* p = Ah + (size_t)mrow * Kw + (it + 1) * 16 + akp0;
            *(uint4*)&wa[0] = *(const uint4*)p;
            *(uint4*)&wa[4] = *(const uint4*)(p + 4);
            const float* p0 = B + (size_t)((it + 1) * 32 + 2 * bkp) * N + ncol;
            float4 r00 = *(const float4*)p0;
            float4 r01 = *(const float4*)(p0 + 4);
            float4 r10 = *(const float4*)(p0 + N);
            float4 r11 = *(const float4*)(p0 + N + 4);
            wb[0] = ph2(r00.x, r10.x); wb[1] = ph2(r00.y, r10.y);
            wb[2] = ph2(r00.z, r10.z); wb[3] = ph2(r00.w, r10.w);
            wb[4] = ph2(r01.x, r11.x); wb[5] = ph2(r01.y, r11.y);
            wb[6] = ph2(r01.z, r11.z); wb[7] = ph2(r01.w, r11.w);
        }

        #pragma unroll
        for (int s = 0; s < 2; ++s) {
            const unsigned* Ar = As[cur] + (s * 4 + tg) * RSTR + (g << 2);
            const unsigned* Br = Bs[cur] + (s * 4 + tg) * PSTR;
            uint4 A0 = *(const uint4*)(Ar + wm * 2);
            uint4 A1 = *(const uint4*)(Ar + (wm + 16) * 2);
            #pragma unroll
            for (int ni = 0; ni < 8; ++ni) {
                int w = (wn + ni * 8 + g) * 2;
                w ^= ((w >> 5) & 7) << 1;
                uint2 bv = *(const uint2*)(Br + w);
                mma_h(c[ni],     A0.x, A0.z, A0.y, A0.w, bv.x, bv.y);
                mma_h(c[8 + ni], A1.x, A1.z, A1.y, A1.w, bv.x, bv.y);
            }
        }

        if (more) {
            store_w8<RSTR>(As[1 - cur], akp0, am, wa);
            unsigned* bb = Bs[1 - cur] + brow * PSTR;
            #pragma unroll
            for (int j = 0; j < 8; ++j) bb[bsw(bn + j, bq)] = wb[j];
            __syncthreads();
        }
    }

    #pragma unroll
    for (int mi = 0; mi < 2; ++mi) {
        #pragma unroll
        for (int ni = 0; ni < 8; ++ni) {
            const float* cc = c[mi * 8 + ni];
            const int row = blockIdx.y * 128 + wm + mi * 16 + g;
            const int col = blockIdx.x * 128 + wn + ni * 8 + 2 * tg;
            *(float2*)&Cf[(size_t)row * N + col]       = make_float2(cc[0], cc[1]);
            *(float2*)&Cf[(size_t)(row + 8) * N + col] = make_float2(cc[2], cc[3]);
        }
    }
}

// ---------------------------------------------------------------------------
extern "C" void kernel_launch(void* const* d_in, const int* in_sizes, int n_in,
                              void* d_out, int out_size)
{
    const float* query = (const float*)d_in[0];
    const float* key   = (const float*)d_in[1];
    const float* value = (const float*)d_in[2];
    const float* wq    = (const float*)d_in[4];
    const float* wk    = (const float*)d_in[5];
    const float* wv    = (const float*)d_in[6];
    const float* wo    = (const float*)d_in[7];

    float* out  = (float*)d_out;
    float* attn = out + (size_t)BB * SDIM * DD;

    unsigned *q, *k, *v, *ctx, *e;
    float* rowsum;
    cudaGetSymbolAddress((void**)&q,      g_q);
    cudaGetSymbolAddress((void**)&k,      g_k);
    cudaGetSymbolAddress((void**)&v,      g_v);
    cudaGetSymbolAddress((void**)&ctx,    g_ctx);
    cudaGetSymbolAddress((void**)&e,      g_e);
    cudaGetSymbolAddress((void**)&rowsum, g_rowsum);

    const dim3 blk(256);

    // Combined QKV projections (one launch, 768 CTAs).
    qkv_h<<<dim3(24, (BB * SDIM) / 128), blk>>>(query, key, value, wq, wk, wv, q, k, v);

    // Fused scores+exp+context.
    fused_attn<<<dim3(SDIM / 128, BB * HH), blk>>>(q, k, v, e, rowsum, ctx);

    // attn output normalization (+ causal zero fill).
    norm_attn<<<BB * HH * SDIM, blk>>>(e, rowsum, attn);

    // Output projection.
    outproj_h<<<dim3(DD / 128, (BB * SDIM) / 128), blk>>>(ctx, wo, out, BB * SDIM, DD, DD);
}

// round 16
// speedup vs baseline: 1.9813x; 1.1519x over previous
#include <cuda_runtime.h>
#include <cuda_fp16.h>

// Problem constants
#define BB   2
#define SDIM 2048
#define DD   1024
#define HH   16
#define DKK  64

// Scratch (device globals; no allocations allowed).
__device__ unsigned g_q[BB * SDIM * DD / 2];
__device__ unsigned g_k[BB * SDIM * DD / 2];
__device__ unsigned g_v[BB * SDIM * DD / 2];
__device__ unsigned g_ctx[BB * SDIM * DD / 2];
__device__ unsigned g_e[(size_t)BB * HH * SDIM * SDIM / 2];  // unnormalized exp, fp16
__device__ float    g_rowsum[BB * HH * SDIM];
// Pre-packed operand images: tile = 8 rows x 256 words (fp16x2), dense.
__device__ unsigned g_wimg[4 * 8 * 32 * 2048];     // weights  [w][bx][it][2048]
__device__ unsigned g_aimg[3 * 32 * 32 * 2048];    // activs   [s][mb][it][2048]

// ---------------------------------------------------------------------------
// FP16 helpers
// ---------------------------------------------------------------------------
__device__ __forceinline__ unsigned ph2(float a, float b) {
    __half2 h = __floats2half2_rn(a, b);
    return *reinterpret_cast<unsigned*>(&h);
}

__device__ __forceinline__ void mma_h(float* c,
                                      unsigned a0, unsigned a1, unsigned a2, unsigned a3,
                                      unsigned b0, unsigned b1) {
    asm volatile(
        "mma.sync.aligned.m16n8k16.row.col.f32.f16.f16.f32 "
        "{%0,%1,%2,%3}, {%4,%5,%6,%7}, {%8,%9}, {%0,%1,%2,%3};"
        : "+f"(c[0]), "+f"(c[1]), "+f"(c[2]), "+f"(c[3])
        : "r"(a0), "r"(a1), "r"(a2), "r"(a3), "r"(b0), "r"(b1));
}

// ---------------------------------------------------------------------------
// Shared layouts, indexed by kp = half2-pair index.
// QUAD: word(m,kp) = row(kp)*264 + mwp(m) + kh(kp); LDS.128 = full A frag.
// PAIR: word(n,kp) = row(kp)*264 + bsw(n, kh(kp)); LDS.64 = B frag.
// row(kp) = (kp&3)+((kp>>3)<<2), kh = (kp>>2)&1. Valid words per row: [0,256).
// Gmem images store dense 8x256 rows; smem keeps stride 264 (bank spread).
// ---------------------------------------------------------------------------
#define RSTR  264
#define PSTR  264
#define PSTRC 136

__device__ __forceinline__ int mwp(int m) {
    return ((m >> 4) << 5) + ((m & 7) << 2) + (((m >> 3) & 1) << 1);
}

template <int STRIDE>
__device__ __forceinline__ void store_w8(unsigned* S, int kp0, int m, const unsigned* w) {
    unsigned* b = S + ((kp0 >> 3) << 2) * STRIDE + mwp(m);
    *(uint2*)(b + 0 * STRIDE) = make_uint2(w[0], w[4]);
    *(uint2*)(b + 1 * STRIDE) = make_uint2(w[1], w[5]);
    *(uint2*)(b + 2 * STRIDE) = make_uint2(w[2], w[6]);
    *(uint2*)(b + 3 * STRIDE) = make_uint2(w[3], w[7]);
}

__device__ __forceinline__ int bsw(int n, int q) {
    int w = n * 2 + q;
    w ^= ((w >> 5) & 7) << 1;
    return w;
}

// Dense image (8x256) -> smem (stride 264) copy helpers.
__device__ __forceinline__ void img_store(unsigned* S, int tid, uint4 u0, uint4 u1) {
    const int t2 = tid + 256;
    *(uint4*)(S + (tid >> 6) * 264 + (tid & 63) * 4) = u0;
    *(uint4*)(S + (t2 >> 6) * 264 + (t2 & 63) * 4)   = u1;
}

// ---------------------------------------------------------------------------
// Weight pre-pack: fp32 W[K,N] -> fp16 PAIR-layout image per (w, bx, it).
// ---------------------------------------------------------------------------
__global__ __launch_bounds__(256)
void prepack_w(const float* __restrict__ w0, const float* __restrict__ w1,
               const float* __restrict__ w2, const float* __restrict__ w3,
               unsigned* __restrict__ wimg)
{
    const int bx = blockIdx.x, it = blockIdx.y, s = blockIdx.z;
    const float* W = (s == 0) ? w0 : (s == 1) ? w1 : (s == 2) ? w2 : w3;
    unsigned* img = wimg + ((size_t)(s * 8 + bx) * 32 + it) * 2048;

    const int kp = threadIdx.x >> 4;          // 0..15
    const int n0 = (threadIdx.x & 15) << 3;   // 0..120
    const int k0 = it * 32 + 2 * kp;
    const float* p = W + (size_t)k0 * DD + bx * 128 + n0;
    float4 r00 = *(const float4*)p;
    float4 r01 = *(const float4*)(p + 4);
    float4 r10 = *(const float4*)(p + DD);
    float4 r11 = *(const float4*)(p + DD + 4);

    const int row = (kp & 3) + ((kp >> 3) << 2);
    const int kh  = (kp >> 2) & 1;
    unsigned* dst = img + row * 256;
    dst[bsw(n0 + 0, kh)] = ph2(r00.x, r10.x);
    dst[bsw(n0 + 1, kh)] = ph2(r00.y, r10.y);
    dst[bsw(n0 + 2, kh)] = ph2(r00.z, r10.z);
    dst[bsw(n0 + 3, kh)] = ph2(r00.w, r10.w);
    dst[bsw(n0 + 4, kh)] = ph2(r01.x, r11.x);
    dst[bsw(n0 + 5, kh)] = ph2(r01.y, r11.y);
    dst[bsw(n0 + 6, kh)] = ph2(r01.z, r11.z);
    dst[bsw(n0 + 7, kh)] = ph2(r01.w, r11.w);
}

// ---------------------------------------------------------------------------
// Activation pre-pack: fp32 X[M,K] -> fp16 QUAD-layout image per (s, mb, it).
// ---------------------------------------------------------------------------
__global__ __launch_bounds__(256)
void prepack_a(const float* __restrict__ x0, const float* __restrict__ x1,
               const float* __restrict__ x2, unsigned* __restrict__ aimg)
{
    const int mb = blockIdx.x, it = blockIdx.y, s = blockIdx.z;
    const float* X = (s == 0) ? x0 : (s == 1) ? x1 : x2;
    unsigned* img = aimg + ((size_t)(s * 32 + mb) * 32 + it) * 2048;

    const int m   = threadIdx.x >> 1;
    const int kp0 = (threadIdx.x & 1) << 3;
    const float* p = X + (size_t)(mb * 128 + m) * DD + it * 32 + (kp0 << 1);
    float4 f0 = *(const float4*)p;
    float4 f1 = *(const float4*)(p + 4);
    float4 f2 = *(const float4*)(p + 8);
    float4 f3 = *(const float4*)(p + 12);
    unsigned w[8];
    w[0] = ph2(f0.x, f0.y); w[1] = ph2(f0.z, f0.w);
    w[2] = ph2(f1.x, f1.y); w[3] = ph2(f1.z, f1.w);
    w[4] = ph2(f2.x, f2.y); w[5] = ph2(f2.z, f2.w);
    w[6] = ph2(f3.x, f3.y); w[7] = ph2(f3.z, f3.w);

    const int base = mwp(m);
    #pragma unroll
    for (int j = 0; j < 8; ++j) {
        const int kp  = kp0 + j;
        const int row = (kp & 3) + ((kp >> 3) << 2);
        const int kh  = (kp >> 2) & 1;
        img[row * 256 + base + kh] = w[j];
    }
}

// ---------------------------------------------------------------------------
// Combined QKV projection from pre-packed images. Pure-copy staging.
// Grid (24, 32): sel = x>>3, bx = x&7, mb = y. 8 warps 4m x 2n, tile 32x64.
// ---------------------------------------------------------------------------
__global__ __launch_bounds__(256, 2)
void qkv_h(const unsigned* __restrict__ aimg, const unsigned* __restrict__ wimg,
           unsigned* __restrict__ Cq, unsigned* __restrict__ Ck,
           unsigned* __restrict__ Cv)
{
    const int sel = blockIdx.x >> 3;
    const int bxl = blockIdx.x & 7;
    const int mb  = blockIdx.y;
    unsigned* C2 = (sel == 0) ? Cq : (sel == 1) ? Ck : Cv;

    const uint4* Aim = (const uint4*)(aimg + ((size_t)(sel * 32 + mb) * 32) * 2048);
    const uint4* Bim = (const uint4*)(wimg + ((size_t)(sel * 8 + bxl) * 32) * 2048);

    __shared__ unsigned As[2][8 * RSTR];
    __shared__ unsigned Bs[2][8 * PSTR];

    const int tid  = threadIdx.x;
    const int lane = tid & 31;
    const int warp = tid >> 5;
    const int g    = lane >> 2;
    const int tg   = lane & 3;
    const int wm   = (warp >> 1) * 32;
    const int wn   = (warp & 1) * 64;

    float c[16][4];
    #pragma unroll
    for (int i = 0; i < 16; ++i)
        #pragma unroll
        for (int j = 0; j < 4; ++j) c[i][j] = 0.f;

    uint4 a0 = Aim[tid], a1 = Aim[tid + 256];
    uint4 b0 = Bim[tid], b1 = Bim[tid + 256];
    img_store(As[0], tid, a0, a1);
    img_store(Bs[0], tid, b0, b1);
    __syncthreads();

    for (int it = 0; it < 32; ++it) {
        const int cur = it & 1;
        const bool more = (it + 1 < 32);
        if (more) {
            a0 = Aim[(it + 1) * 512 + tid]; a1 = Aim[(it + 1) * 512 + tid + 256];
            b0 = Bim[(it + 1) * 512 + tid]; b1 = Bim[(it + 1) * 512 + tid + 256];
        }

        #pragma unroll
        for (int s = 0; s < 2; ++s) {
            const unsigned* Ar = As[cur] + (s * 4 + tg) * RSTR + (g << 2);
            const unsigned* Br = Bs[cur] + (s * 4 + tg) * PSTR;
            uint4 A0 = *(const uint4*)(Ar + wm * 2);
            uint4 A1 = *(const uint4*)(Ar + (wm + 16) * 2);
            #pragma unroll
            for (int ni = 0; ni < 8; ++ni) {
                int w = (wn + ni * 8 + g) * 2;
                w ^= ((w >> 5) & 7) << 1;
                uint2 bv = *(const uint2*)(Br + w);
                mma_h(c[ni],     A0.x, A0.z, A0.y, A0.w, bv.x, bv.y);
                mma_h(c[8 + ni], A1.x, A1.z, A1.y, A1.w, bv.x, bv.y);
            }
        }

        if (more) {
            img_store(As[1 - cur], tid, a0, a1);
            img_store(Bs[1 - cur], tid, b0, b1);
            __syncthreads();
        }
    }

    #pragma unroll
    for (int mi = 0; mi < 2; ++mi) {
        #pragma unroll
        for (int ni = 0; ni < 8; ++ni) {
            const float* cc = c[mi * 8 + ni];
            const int row = mb * 128 + wm + mi * 16 + g;
            const int col = bxl * 128 + wn + ni * 8 + 2 * tg;
            C2[(size_t)row * (DD / 2) + (col >> 1)]       = ph2(cc[0], cc[1]);
            C2[(size_t)(row + 8) * (DD / 2) + (col >> 1)] = ph2(cc[2], cc[3]);
        }
    }
}

// ---------------------------------------------------------------------------
// Fused attention (verified R13): S = QK^T, E = exp(S/8) masked, O += E·V,
// E spilled fp16, ctx = O/rowsum.
// ---------------------------------------------------------------------------
__global__ __launch_bounds__(256)
void fused_attn(const unsigned* __restrict__ q2, const unsigned* __restrict__ k2,
                const unsigned* __restrict__ v2, unsigned* __restrict__ e2,
                float* __restrict__ rowsum, unsigned* __restrict__ ctx2)
{
    const int by = (SDIM / 128 - 1) - blockIdx.x;
    const int z  = blockIdx.y;
    const int b  = z >> 4;
    const int h  = z & 15;

    __shared__ unsigned Qs[16 * RSTR];
    __shared__ unsigned Ks[16 * RSTR];
    __shared__ unsigned Vs[32 * PSTRC];

    const int tid  = threadIdx.x;
    const int lane = tid & 31;
    const int warp = tid >> 5;
    const int g    = lane >> 2;
    const int tg   = lane & 3;
    const int wm   = warp * 16;

    const int r   = tid >> 1;
    const int kp0 = (tid & 1) << 4;
    const int vkp  = tid >> 2;
    const int vrow = (vkp & 3) + ((vkp >> 3) << 2);
    const int vq   = (vkp >> 2) & 1;
    const int vc0  = (tid & 3) << 4;

    {
        const unsigned* qp = q2 + (size_t)(b * SDIM + by * 128 + r) * (DD / 2) + h * 32 + kp0;
        unsigned w[16];
        *(uint4*)&w[0]  = *(const uint4*)qp;
        *(uint4*)&w[4]  = *(const uint4*)(qp + 4);
        *(uint4*)&w[8]  = *(const uint4*)(qp + 8);
        *(uint4*)&w[12] = *(const uint4*)(qp + 12);
        store_w8<RSTR>(Qs, kp0,     r, w);
        store_w8<RSTR>(Qs, kp0 + 8, r, w + 8);
    }

    float co[8][4];
    #pragma unroll
    for (int i = 0; i < 8; ++i)
        #pragma unroll
        for (int j = 0; j < 4; ++j) co[i][j] = 0.f;
    float rs0 = 0.f, rs1 = 0.f;

    const int i0 = by * 128 + wm + g;

    for (int bx = 0; bx <= by; ++bx) {
        __syncthreads();
        {
            const unsigned* kp = k2 + (size_t)(b * SDIM + bx * 128 + r) * (DD / 2) + h * 32 + kp0;
            unsigned w[16];
            *(uint4*)&w[0]  = *(const uint4*)kp;
            *(uint4*)&w[4]  = *(const uint4*)(kp + 4);
            *(uint4*)&w[8]  = *(const uint4*)(kp + 8);
            *(uint4*)&w[12] = *(const uint4*)(kp + 12);
            store_w8<RSTR>(Ks, kp0,     r, w);
            store_w8<RSTR>(Ks, kp0 + 8, r, w + 8);
        }
        {
            const unsigned* vp = v2 + (size_t)(b * SDIM + bx * 128 + 2 * vkp) * (DD / 2)
                                 + h * 32 + (vc0 >> 1);
            unsigned r0[8], r1[8];
            *(uint4*)&r0[0] = *(const uint4*)vp;
            *(uint4*)&r0[4] = *(const uint4*)(vp + 4);
            *(uint4*)&r1[0] = *(const uint4*)(vp + DD / 2);
            *(uint4*)&r1[4] = *(const uint4*)(vp + DD / 2 + 4);
            const __half* h0 = (const __half*)r0;
            const __half* h1 = (const __half*)r1;
            unsigned* bb = Vs + vrow * PSTRC;
            #pragma unroll
            for (int j = 0; j < 16; ++j) {
                __half2 hh = __halves2half2(h0[j], h1[j]);
                bb[bsw(vc0 + j, vq)] = *(unsigned*)&hh;
            }
        }
        __syncthreads();

        const bool diag = (bx == by);
        #pragma unroll
        for (int half = 0; half < 2; ++half) {
            float cs[8][4];
            #pragma unroll
            for (int i = 0; i < 8; ++i)
                #pragma unroll
                for (int j = 0; j < 4; ++j) cs[i][j] = 0.f;

            #pragma unroll
            for (int s = 0; s < 4; ++s) {
                const unsigned* Ar = Qs + (s * 4 + tg) * RSTR + (g << 2);
                const unsigned* Br = Ks + (s * 4 + tg) * RSTR + (g << 2);
                uint4 A0 = *(const uint4*)(Ar + wm * 2);
                #pragma unroll
                for (int np = 0; np < 4; ++np) {
                    uint4 Bv = *(const uint4*)(Br + (half * 64 + np * 16) * 2);
                    mma_h(cs[2 * np],     A0.x, A0.z, A0.y, A0.w, Bv.x, Bv.y);
                    mma_h(cs[2 * np + 1], A0.x, A0.z, A0.y, A0.w, Bv.z, Bv.w);
                }
            }

            unsigned ea[4][4];
            #pragma unroll
            for (int ni = 0; ni < 8; ++ni) {
                const int j0 = bx * 128 + half * 64 + ni * 8 + 2 * tg;
                float e00 = __expf(cs[ni][0] * 0.125f);
                float e01 = __expf(cs[ni][1] * 0.125f);
                float e10 = __expf(cs[ni][2] * 0.125f);
                float e11 = __expf(cs[ni][3] * 0.125f);
                if (diag) {
                    if (j0     > i0)     e00 = 0.f;
                    if (j0 + 1 > i0)     e01 = 0.f;
                    if (j0     > i0 + 8) e10 = 0.f;
                    if (j0 + 1 > i0 + 8) e11 = 0.f;
                }
                rs0 += e00 + e01;
                rs1 += e10 + e11;
                const unsigned w0 = ph2(e00, e01);
                const unsigned w1 = ph2(e10, e11);
                e2[((size_t)z * SDIM + i0) * (SDIM / 2) + (j0 >> 1)]     = w0;
                e2[((size_t)z * SDIM + i0 + 8) * (SDIM / 2) + (j0 >> 1)] = w1;
                ea[ni >> 1][(ni & 1) * 2 + 0] = w0;
                ea[ni >> 1][(ni & 1) * 2 + 1] = w1;
            }

            #pragma unroll
            for (int t = 0; t < 4; ++t) {
                const int kt = half * 4 + t;
                const unsigned* Br = Vs + (kt * 4 + tg) * PSTRC;
                #pragma unroll
                for (int nj = 0; nj < 8; ++nj) {
                    int w = (nj * 8 + g) * 2;
                    w ^= ((w >> 5) & 7) << 1;
                    uint2 bv = *(const uint2*)(Br + w);
                    mma_h(co[nj], ea[t][0], ea[t][1], ea[t][2], ea[t][3], bv.x, bv.y);
                }
            }
        }
    }

    rs0 += __shfl_xor_sync(0xffffffffu, rs0, 1);
    rs0 += __shfl_xor_sync(0xffffffffu, rs0, 2);
    rs1 += __shfl_xor_sync(0xffffffffu, rs1, 1);
    rs1 += __shfl_xor_sync(0xffffffffu, rs1, 2);
    if (tg == 0) {
        rowsum[(size_t)z * SDIM + i0]     = rs0;
        rowsum[(size_t)z * SDIM + i0 + 8] = rs1;
    }
    const float inv0 = 1.f / rs0;
    const float inv1 = 1.f / rs1;

    #pragma unroll
    for (int nj = 0; nj < 8; ++nj) {
        const int wcol = h * 32 + nj * 4 + tg;
        ctx2[(size_t)(b * SDIM + i0) * (DD / 2) + wcol]     = ph2(co[nj][0] * inv0, co[nj][1] * inv0);
        ctx2[(size_t)(b * SDIM + i0 + 8) * (DD / 2) + wcol] = ph2(co[nj][2] * inv1, co[nj][3] * inv1);
    }
}

// ---------------------------------------------------------------------------
// Normalize: attn[r][j] = E[r][j] / rowsum[r] (fp16 -> fp32), zero-fill tail.
// ---------------------------------------------------------------------------
__global__ __launch_bounds__(256)
void norm_attn(const unsigned* __restrict__ e2, const float* __restrict__ rowsum,
               float* __restrict__ attn)
{
    const int r   = blockIdx.x;
    const int i   = r & (SDIM - 1);
    const int L   = ((i >> 7) + 1) << 7;
    const int tid = threadIdx.x;
    const float inv = 1.f / rowsum[r];
    const unsigned* erow = e2 + (size_t)r * (SDIM / 2);
    float* orow = attn + (size_t)r * SDIM;

    for (int q = tid; q < (L >> 2); q += 256) {
        uint2 ew = *(const uint2*)(erow + q * 2);
        __half2 h0 = *(__half2*)&ew.x;
        __half2 h1 = *(__half2*)&ew.y;
        float2 f0 = __half22float2(h0);
        float2 f1 = __half22float2(h1);
        float4 o = make_float4(f0.x * inv, f0.y * inv, f1.x * inv, f1.y * inv);
        *(float4*)(orow + q * 4) = o;
    }
    const float4 z4 = make_float4(0.f, 0.f, 0.f, 0.f);
    for (int q = (L >> 2) + tid; q < (SDIM >> 2); q += 256)
        *(float4*)(orow + q * 4) = z4;
}

// ---------------------------------------------------------------------------
// Output projection: fp16 ctx A (linear), B from pre-packed image, fp32 C.
// ---------------------------------------------------------------------------
__global__ __launch_bounds__(256, 2)
void outproj_h(const unsigned* __restrict__ Ah, const unsigned* __restrict__ wimg,
               float* __restrict__ Cf)
{
    const int N = DD, Kw = DD / 2;
    const uint4* Bim = (const uint4*)(wimg + ((size_t)(3 * 8 + blockIdx.x) * 32) * 2048);

    __shared__ unsigned As[2][8 * RSTR];
    __shared__ unsigned Bs[2][8 * PSTR];

    const int tid  = threadIdx.x;
    const int lane = tid & 31;
    const int warp = tid >> 5;
    const int g    = lane >> 2;
    const int tg   = lane & 3;
    const int wm   = (warp >> 1) * 32;
    const int wn   = (warp & 1) * 64;

    const int am   = tid >> 1;
    const int akp0 = (tid & 1) << 3;

    unsigned wa[8];
    float c[16][4];
    #pragma unroll
    for (int i = 0; i < 16; ++i)
        #pragma unroll
        for (int j = 0; j < 4; ++j) c[i][j] = 0.f;

    const int mrow = blockIdx.y * 128 + am;

    {
        const unsigned* p = Ah + (size_t)mrow * Kw + akp0;
        *(uint4*)&wa[0] = *(const uint4*)p;
        *(uint4*)&wa[4] = *(const uint4*)(p + 4);
        store_w8<RSTR>(As[0], akp0, am, wa);
        uint4 b0 = Bim[tid], b1 = Bim[tid + 256];
        img_store(Bs[0], tid, b0, b1);
    }
    __syncthreads();

    for (int it = 0; it < 32; ++it) {
        const int cur = it & 1;
        const bool more = (it + 1 < 32);
        uint4 b0, b1;
        if (more) {
            const unsigned* p = Ah + (size_t)mrow * Kw + (it + 1) * 16 + akp0;
            *(uint4*)&wa[0] = *(const uint4*)p;
            *(uint4*)&wa[4] = *(const uint4*)(p + 4);
            b0 = Bim[(it + 1) * 512 + tid];
            b1 = Bim[(it + 1) * 512 + tid + 256];
        }

        #pragma unroll
        for (int s = 0; s < 2; ++s) {
            const unsigned* Ar = As[cur] + (s * 4 + tg) * RSTR + (g << 2);
            const unsigned* Br = Bs[cur] + (s * 4 + tg) * PSTR;
            uint4 A0 = *(const uint4*)(Ar + wm * 2);
            uint4 A1 = *(const uint4*)(Ar + (wm + 16) * 2);
            #pragma unroll
            for (int ni = 0; ni < 8; ++ni) {
                int w = (wn + ni * 8 + g) * 2;
                w ^= ((w >> 5) & 7) << 1;
                uint2 bv = *(const uint2*)(Br + w);
                mma_h(c[ni],     A0.x, A0.z, A0.y, A0.w, bv.x, bv.y);
                mma_h(c[8 + ni], A1.x, A1.z, A1.y, A1.w, bv.x, bv.y);
            }
        }

        if (more) {
            store_w8<RSTR>(As[1 - cur], akp0, am, wa);
            img_store(Bs[1 - cur], tid, b0, b1);
            __syncthreads();
        }
    }

    #pragma unroll
    for (int mi = 0; mi < 2; ++mi) {
        #pragma unroll
        for (int ni = 0; ni < 8; ++ni) {
            const float* cc = c[mi * 8 + ni];
            const int row = blockIdx.y * 128 + wm + mi * 16 + g;
            const int col = blockIdx.x * 128 + wn + ni * 8 + 2 * tg;
            *(float2*)&Cf[(size_t)row * N + col]       = make_float2(cc[0], cc[1]);
            *(float2*)&Cf[(size_t)(row + 8) * N + col] = make_float2(cc[2], cc[3]);
        }
    }
}

// ---------------------------------------------------------------------------
extern "C" void kernel_launch(void* const* d_in, const int* in_sizes, int n_in,
                              void* d_out, int out_size)
{
    const float* query = (const float*)d_in[0];
    const float* key   = (const float*)d_in[1];
    const float* value = (const float*)d_in[2];
    const float* wq    = (const float*)d_in[4];
    const float* wk    = (const float*)d_in[5];
    const float* wv    = (const float*)d_in[6];
    const float* wo    = (const float*)d_in[7];

    float* out  = (float*)d_out;
    float* attn = out + (size_t)BB * SDIM * DD;

    unsigned *q, *k, *v, *ctx, *e, *wimg, *aimg;
    float* rowsum;
    cudaGetSymbolAddress((void**)&q,      g_q);
    cudaGetSymbolAddress((void**)&k,      g_k);
    cudaGetSymbolAddress((void**)&v,      g_v);
    cudaGetSymbolAddress((void**)&ctx,    g_ctx);
    cudaGetSymbolAddress((void**)&e,      g_e);
    cudaGetSymbolAddress((void**)&rowsum, g_rowsum);
    cudaGetSymbolAddress((void**)&wimg,   g_wimg);
    cudaGetSymbolAddress((void**)&aimg,   g_aimg);

    const dim3 blk(256);

    // Pre-pack operands into smem-image layout (fp16).
    prepack_w<<<dim3(8, 32, 4), blk>>>(wq, wk, wv, wo, wimg);
    prepack_a<<<dim3(32, 32, 3), blk>>>(query, key, value, aimg);

    // Combined QKV projections.
    qkv_h<<<dim3(24, (BB * SDIM) / 128), blk>>>(aimg, wimg, q, k, v);

    // Fused scores+exp+context.
    fused_attn<<<dim3(SDIM / 128, BB * HH), blk>>>(q, k, v, e, rowsum, ctx);

    // attn output normalization (+ causal zero fill).
    norm_attn<<<BB * HH * SDIM, blk>>>(e, rowsum, attn);

    // Output projection.
    outproj_h<<<dim3(DD / 128, (BB * SDIM) / 128), blk>>>(ctx, wimg, out);
}

// round 17
// speedup vs baseline: 2.3347x; 1.1784x over previous
#include <cuda_runtime.h>
#include <cuda_fp16.h>

// Problem constants
#define BB   2
#define SDIM 2048
#define DD   1024
#define HH   16
#define DKK  64

// Scratch (device globals; no allocations allowed).
__device__ unsigned g_q[BB * SDIM * DD / 2];
__device__ unsigned g_k[BB * SDIM * DD / 2];
__device__ unsigned g_v[BB * SDIM * DD / 2];
__device__ unsigned g_ctx[BB * SDIM * DD / 2];
// E blob: fp16 fragments, [(z*16+by)*32 + bx*2+half][warp][t][lane] (uint4 units)
__device__ unsigned g_e[(size_t)BB * HH * SDIM * SDIM / 2];
__device__ float    g_rowsum[BB * HH * SDIM];
// Pre-packed operand images: tile = 8 rows x 256 words (fp16x2), dense.
__device__ unsigned g_wimg[4 * 8 * 32 * 2048];     // weights  [w][bx][it][2048]
__device__ unsigned g_aimg[3 * 32 * 32 * 2048];    // activs   [s][mb][it][2048]

// ---------------------------------------------------------------------------
// FP16 helpers
// ---------------------------------------------------------------------------
__device__ __forceinline__ unsigned ph2(float a, float b) {
    __half2 h = __floats2half2_rn(a, b);
    return *reinterpret_cast<unsigned*>(&h);
}

__device__ __forceinline__ void mma_h(float* c,
                                      unsigned a0, unsigned a1, unsigned a2, unsigned a3,
                                      unsigned b0, unsigned b1) {
    asm volatile(
        "mma.sync.aligned.m16n8k16.row.col.f32.f16.f16.f32 "
        "{%0,%1,%2,%3}, {%4,%5,%6,%7}, {%8,%9}, {%0,%1,%2,%3};"
        : "+f"(c[0]), "+f"(c[1]), "+f"(c[2]), "+f"(c[3])
        : "r"(a0), "r"(a1), "r"(a2), "r"(a3), "r"(b0), "r"(b1));
}

// ---------------------------------------------------------------------------
// Shared layouts, indexed by kp = half2-pair index.
// QUAD: word(m,kp) = row(kp)*264 + mwp(m) + kh(kp); LDS.128 = full A frag.
// PAIR: word(n,kp) = row(kp)*264 + bsw(n, kh(kp)); LDS.64 = B frag.
// ---------------------------------------------------------------------------
#define RSTR  264
#define PSTR  264
#define PSTRC 136

__device__ __forceinline__ int mwp(int m) {
    return ((m >> 4) << 5) + ((m & 7) << 2) + (((m >> 3) & 1) << 1);
}

template <int STRIDE>
__device__ __forceinline__ void store_w8(unsigned* S, int kp0, int m, const unsigned* w) {
    unsigned* b = S + ((kp0 >> 3) << 2) * STRIDE + mwp(m);
    *(uint2*)(b + 0 * STRIDE) = make_uint2(w[0], w[4]);
    *(uint2*)(b + 1 * STRIDE) = make_uint2(w[1], w[5]);
    *(uint2*)(b + 2 * STRIDE) = make_uint2(w[2], w[6]);
    *(uint2*)(b + 3 * STRIDE) = make_uint2(w[3], w[7]);
}

__device__ __forceinline__ int bsw(int n, int q) {
    int w = n * 2 + q;
    w ^= ((w >> 5) & 7) << 1;
    return w;
}

__device__ __forceinline__ void img_store(unsigned* S, int tid, uint4 u0, uint4 u1) {
    const int t2 = tid + 256;
    *(uint4*)(S + (tid >> 6) * 264 + (tid & 63) * 4) = u0;
    *(uint4*)(S + (t2 >> 6) * 264 + (t2 & 63) * 4)   = u1;
}

// ---------------------------------------------------------------------------
// Weight pre-pack: fp32 W[K,N] -> fp16 PAIR-layout image per (w, bx, it).
// ---------------------------------------------------------------------------
__global__ __launch_bounds__(256)
void prepack_w(const float* __restrict__ w0, const float* __restrict__ w1,
               const float* __restrict__ w2, const float* __restrict__ w3,
               unsigned* __restrict__ wimg)
{
    const int bx = blockIdx.x, it = blockIdx.y, s = blockIdx.z;
    const float* W = (s == 0) ? w0 : (s == 1) ? w1 : (s == 2) ? w2 : w3;
    unsigned* img = wimg + ((size_t)(s * 8 + bx) * 32 + it) * 2048;

    const int kp = threadIdx.x >> 4;
    const int n0 = (threadIdx.x & 15) << 3;
    const int k0 = it * 32 + 2 * kp;
    const float* p = W + (size_t)k0 * DD + bx * 128 + n0;
    float4 r00 = *(const float4*)p;
    float4 r01 = *(const float4*)(p + 4);
    float4 r10 = *(const float4*)(p + DD);
    float4 r11 = *(const float4*)(p + DD + 4);

    const int row = (kp & 3) + ((kp >> 3) << 2);
    const int kh  = (kp >> 2) & 1;
    unsigned* dst = img + row * 256;
    dst[bsw(n0 + 0, kh)] = ph2(r00.x, r10.x);
    dst[bsw(n0 + 1, kh)] = ph2(r00.y, r10.y);
    dst[bsw(n0 + 2, kh)] = ph2(r00.z, r10.z);
    dst[bsw(n0 + 3, kh)] = ph2(r00.w, r10.w);
    dst[bsw(n0 + 4, kh)] = ph2(r01.x, r11.x);
    dst[bsw(n0 + 5, kh)] = ph2(r01.y, r11.y);
    dst[bsw(n0 + 6, kh)] = ph2(r01.z, r11.z);
    dst[bsw(n0 + 7, kh)] = ph2(r01.w, r11.w);
}

// ---------------------------------------------------------------------------
// Activation pre-pack: fp32 X[M,K] -> fp16 QUAD-layout image per (s, mb, it).
// ---------------------------------------------------------------------------
__global__ __launch_bounds__(256)
void prepack_a(const float* __restrict__ x0, const float* __restrict__ x1,
               const float* __restrict__ x2, unsigned* __restrict__ aimg)
{
    const int mb = blockIdx.x, it = blockIdx.y, s = blockIdx.z;
    const float* X = (s == 0) ? x0 : (s == 1) ? x1 : x2;
    unsigned* img = aimg + ((size_t)(s * 32 + mb) * 32 + it) * 2048;

    const int m   = threadIdx.x >> 1;
    const int kp0 = (threadIdx.x & 1) << 3;
    const float* p = X + (size_t)(mb * 128 + m) * DD + it * 32 + (kp0 << 1);
    float4 f0 = *(const float4*)p;
    float4 f1 = *(const float4*)(p + 4);
    float4 f2 = *(const float4*)(p + 8);
    float4 f3 = *(const float4*)(p + 12);
    unsigned w[8];
    w[0] = ph2(f0.x, f0.y); w[1] = ph2(f0.z, f0.w);
    w[2] = ph2(f1.x, f1.y); w[3] = ph2(f1.z, f1.w);
    w[4] = ph2(f2.x, f2.y); w[5] = ph2(f2.z, f2.w);
    w[6] = ph2(f3.x, f3.y); w[7] = ph2(f3.z, f3.w);

    const int base = mwp(m);
    #pragma unroll
    for (int j = 0; j < 8; ++j) {
        const int kp  = kp0 + j;
        const int row = (kp & 3) + ((kp >> 3) << 2);
        const int kh  = (kp >> 2) & 1;
        img[row * 256 + base + kh] = w[j];
    }
}

// ---------------------------------------------------------------------------
// Combined QKV projection from pre-packed images. Pure-copy staging.
// ---------------------------------------------------------------------------
__global__ __launch_bounds__(256, 2)
void qkv_h(const unsigned* __restrict__ aimg, const unsigned* __restrict__ wimg,
           unsigned* __restrict__ Cq, unsigned* __restrict__ Ck,
           unsigned* __restrict__ Cv)
{
    const int sel = blockIdx.x >> 3;
    const int bxl = blockIdx.x & 7;
    const int mb  = blockIdx.y;
    unsigned* C2 = (sel == 0) ? Cq : (sel == 1) ? Ck : Cv;

    const uint4* Aim = (const uint4*)(aimg + ((size_t)(sel * 32 + mb) * 32) * 2048);
    const uint4* Bim = (const uint4*)(wimg + ((size_t)(sel * 8 + bxl) * 32) * 2048);

    __shared__ unsigned As[2][8 * RSTR];
    __shared__ unsigned Bs[2][8 * PSTR];

    const int tid  = threadIdx.x;
    const int lane = tid & 31;
    const int warp = tid >> 5;
    const int g    = lane >> 2;
    const int tg   = lane & 3;
    const int wm   = (warp >> 1) * 32;
    const int wn   = (warp & 1) * 64;

    float c[16][4];
    #pragma unroll
    for (int i = 0; i < 16; ++i)
        #pragma unroll
        for (int j = 0; j < 4; ++j) c[i][j] = 0.f;

    uint4 a0 = Aim[tid], a1 = Aim[tid + 256];
    uint4 b0 = Bim[tid], b1 = Bim[tid + 256];
    img_store(As[0], tid, a0, a1);
    img_store(Bs[0], tid, b0, b1);
    __syncthreads();

    for (int it = 0; it < 32; ++it) {
        const int cur = it & 1;
        const bool more = (it + 1 < 32);
        if (more) {
            a0 = Aim[(it + 1) * 512 + tid]; a1 = Aim[(it + 1) * 512 + tid + 256];
            b0 = Bim[(it + 1) * 512 + tid]; b1 = Bim[(it + 1) * 512 + tid + 256];
        }

        #pragma unroll
        for (int s = 0; s < 2; ++s) {
            const unsigned* Ar = As[cur] + (s * 4 + tg) * RSTR + (g << 2);
            const unsigned* Br = Bs[cur] + (s * 4 + tg) * PSTR;
            uint4 A0 = *(const uint4*)(Ar + wm * 2);
            uint4 A1 = *(const uint4*)(Ar + (wm + 16) * 2);
            #pragma unroll
            for (int ni = 0; ni < 8; ++ni) {
                int w = (wn + ni * 8 + g) * 2;
                w ^= ((w >> 5) & 7) << 1;
                uint2 bv = *(const uint2*)(Br + w);
                mma_h(c[ni],     A0.x, A0.z, A0.y, A0.w, bv.x, bv.y);
                mma_h(c[8 + ni], A1.x, A1.z, A1.y, A1.w, bv.x, bv.y);
            }
        }

        if (more) {
            img_store(As[1 - cur], tid, a0, a1);
            img_store(Bs[1 - cur], tid, b0, b1);
            __syncthreads();
        }
    }

    #pragma unroll
    for (int mi = 0; mi < 2; ++mi) {
        #pragma unroll
        for (int ni = 0; ni < 8; ++ni) {
            const float* cc = c[mi * 8 + ni];
            const int row = mb * 128 + wm + mi * 16 + g;
            const int col = bxl * 128 + wn + ni * 8 + 2 * tg;
            C2[(size_t)row * (DD / 2) + (col >> 1)]       = ph2(cc[0], cc[1]);
            C2[(size_t)(row + 8) * (DD / 2) + (col >> 1)] = ph2(cc[2], cc[3]);
        }
    }
}

// ---------------------------------------------------------------------------
// Fused attention: S = QK^T, E = exp(S/8) masked, O += E·V.
// E spilled to fragment-layout blob with 4x STG.128 per half-tile.
// 1D heavy-first grid: bid>>5 -> by (descending), bid&31 -> z.
// ---------------------------------------------------------------------------
__global__ __launch_bounds__(256)
void fused_attn(const unsigned* __restrict__ q2, const unsigned* __restrict__ k2,
                const unsigned* __restrict__ v2, unsigned* __restrict__ e2,
                float* __restrict__ rowsum, unsigned* __restrict__ ctx2)
{
    const int by = (SDIM / 128 - 1) - (blockIdx.x >> 5);
    const int z  = blockIdx.x & 31;
    const int b  = z >> 4;
    const int h  = z & 15;

    __shared__ unsigned Qs[16 * RSTR];
    __shared__ unsigned Ks[16 * RSTR];
    __shared__ unsigned Vs[32 * PSTRC];

    const int tid  = threadIdx.x;
    const int lane = tid & 31;
    const int warp = tid >> 5;
    const int g    = lane >> 2;
    const int tg   = lane & 3;
    const int wm   = warp * 16;

    const int r   = tid >> 1;
    const int kp0 = (tid & 1) << 4;
    const int vkp  = tid >> 2;
    const int vrow = (vkp & 3) + ((vkp >> 3) << 2);
    const int vq   = (vkp >> 2) & 1;
    const int vc0  = (tid & 3) << 4;

    {
        const unsigned* qp = q2 + (size_t)(b * SDIM + by * 128 + r) * (DD / 2) + h * 32 + kp0;
        unsigned w[16];
        *(uint4*)&w[0]  = *(const uint4*)qp;
        *(uint4*)&w[4]  = *(const uint4*)(qp + 4);
        *(uint4*)&w[8]  = *(const uint4*)(qp + 8);
        *(uint4*)&w[12] = *(const uint4*)(qp + 12);
        store_w8<RSTR>(Qs, kp0,     r, w);
        store_w8<RSTR>(Qs, kp0 + 8, r, w + 8);
    }

    float co[8][4];
    #pragma unroll
    for (int i = 0; i < 8; ++i)
        #pragma unroll
        for (int j = 0; j < 4; ++j) co[i][j] = 0.f;
    float rs0 = 0.f, rs1 = 0.f;

    const int i0 = by * 128 + wm + g;
    unsigned* blobw = e2 + ((size_t)(z * 16 + by) * 32) * 4096 + warp * 512 + lane * 4;

    for (int bx = 0; bx <= by; ++bx) {
        __syncthreads();
        {
            const unsigned* kp = k2 + (size_t)(b * SDIM + bx * 128 + r) * (DD / 2) + h * 32 + kp0;
            unsigned w[16];
            *(uint4*)&w[0]  = *(const uint4*)kp;
            *(uint4*)&w[4]  = *(const uint4*)(kp + 4);
            *(uint4*)&w[8]  = *(const uint4*)(kp + 8);
            *(uint4*)&w[12] = *(const uint4*)(kp + 12);
            store_w8<RSTR>(Ks, kp0,     r, w);
            store_w8<RSTR>(Ks, kp0 + 8, r, w + 8);
        }
        {
            const unsigned* vp = v2 + (size_t)(b * SDIM + bx * 128 + 2 * vkp) * (DD / 2)
                                 + h * 32 + (vc0 >> 1);
            unsigned r0[8], r1[8];
            *(uint4*)&r0[0] = *(const uint4*)vp;
            *(uint4*)&r0[4] = *(const uint4*)(vp + 4);
            *(uint4*)&r1[0] = *(const uint4*)(vp + DD / 2);
            *(uint4*)&r1[4] = *(const uint4*)(vp + DD / 2 + 4);
            const __half* h0 = (const __half*)r0;
            const __half* h1 = (const __half*)r1;
            unsigned* bb = Vs + vrow * PSTRC;
            #pragma unroll
            for (int j = 0; j < 16; ++j) {
                __half2 hh = __halves2half2(h0[j], h1[j]);
                bb[bsw(vc0 + j, vq)] = *(unsigned*)&hh;
            }
        }
        __syncthreads();

        const bool diag = (bx == by);
        #pragma unroll
        for (int half = 0; half < 2; ++half) {
            float cs[8][4];
            #pragma unroll
            for (int i = 0; i < 8; ++i)
                #pragma unroll
                for (int j = 0; j < 4; ++j) cs[i][j] = 0.f;

            #pragma unroll
            for (int s = 0; s < 4; ++s) {
                const unsigned* Ar = Qs + (s * 4 + tg) * RSTR + (g << 2);
                const unsigned* Br = Ks + (s * 4 + tg) * RSTR + (g << 2);
                uint4 A0 = *(const uint4*)(Ar + wm * 2);
                #pragma unroll
                for (int np = 0; np < 4; ++np) {
                    uint4 Bv = *(const uint4*)(Br + (half * 64 + np * 16) * 2);
                    mma_h(cs[2 * np],     A0.x, A0.z, A0.y, A0.w, Bv.x, Bv.y);
                    mma_h(cs[2 * np + 1], A0.x, A0.z, A0.y, A0.w, Bv.z, Bv.w);
                }
            }

            unsigned ea[4][4];
            #pragma unroll
            for (int ni = 0; ni < 8; ++ni) {
                const int j0 = bx * 128 + half * 64 + ni * 8 + 2 * tg;
                float e00 = __expf(cs[ni][0] * 0.125f);
                float e01 = __expf(cs[ni][1] * 0.125f);
                float e10 = __expf(cs[ni][2] * 0.125f);
                float e11 = __expf(cs[ni][3] * 0.125f);
                if (diag) {
                    if (j0     > i0)     e00 = 0.f;
                    if (j0 + 1 > i0)     e01 = 0.f;
                    if (j0     > i0 + 8) e10 = 0.f;
                    if (j0 + 1 > i0 + 8) e11 = 0.f;
                }
                rs0 += e00 + e01;
                rs1 += e10 + e11;
                ea[ni >> 1][(ni & 1) * 2 + 0] = ph2(e00, e01);
                ea[ni >> 1][(ni & 1) * 2 + 1] = ph2(e10, e11);
            }

            // E -> blob, coalesced STG.128 x4.
            {
                unsigned* bp = blobw + (size_t)(bx * 2 + half) * 4096;
                #pragma unroll
                for (int t = 0; t < 4; ++t)
                    *(uint4*)(bp + t * 128) =
                        make_uint4(ea[t][0], ea[t][1], ea[t][2], ea[t][3]);
            }

            #pragma unroll
            for (int t = 0; t < 4; ++t) {
                const int kt = half * 4 + t;
                const unsigned* Br = Vs + (kt * 4 + tg) * PSTRC;
                #pragma unroll
                for (int nj = 0; nj < 8; ++nj) {
                    int w = (nj * 8 + g) * 2;
                    w ^= ((w >> 5) & 7) << 1;
                    uint2 bv = *(const uint2*)(Br + w);
                    mma_h(co[nj], ea[t][0], ea[t][1], ea[t][2], ea[t][3], bv.x, bv.y);
                }
            }
        }
    }

    rs0 += __shfl_xor_sync(0xffffffffu, rs0, 1);
    rs0 += __shfl_xor_sync(0xffffffffu, rs0, 2);
    rs1 += __shfl_xor_sync(0xffffffffu, rs1, 1);
    rs1 += __shfl_xor_sync(0xffffffffu, rs1, 2);
    if (tg == 0) {
        rowsum[(size_t)z * SDIM + i0]     = rs0;
        rowsum[(size_t)z * SDIM + i0 + 8] = rs1;
    }
    const float inv0 = 1.f / rs0;
    const float inv1 = 1.f / rs1;

    #pragma unroll
    for (int nj = 0; nj < 8; ++nj) {
        const int wcol = h * 32 + nj * 4 + tg;
        ctx2[(size_t)(b * SDIM + i0) * (DD / 2) + wcol]     = ph2(co[nj][0] * inv0, co[nj][1] * inv0);
        ctx2[(size_t)(b * SDIM + i0 + 8) * (DD / 2) + wcol] = ph2(co[nj][2] * inv1, co[nj][3] * inv1);
    }
}

// ---------------------------------------------------------------------------
// Normalize + decode E blob -> fp32 attn, zero-fill causal tail.
// One block per (z, by, warp) = 16 rows. Coalesced uint4 reads.
// Thread: cq = tid>>7 (chunk parity), q = tid&127 -> t = q>>5, lane = q&31.
// ---------------------------------------------------------------------------
__global__ __launch_bounds__(256)
void norm_attn(const unsigned* __restrict__ e2, const float* __restrict__ rowsum,
               float* __restrict__ attn)
{
    const int warp = blockIdx.x & 7;
    const int zby  = blockIdx.x >> 3;
    const int by   = zby & 15;
    const int z    = zby >> 4;

    const int tid  = threadIdx.x;
    const int cq   = tid >> 7;
    const int q    = tid & 127;
    const int t    = q >> 5;
    const int lane = q & 31;
    const int g    = lane >> 2;
    const int tg   = lane & 3;

    const int i0 = by * 128 + warp * 16 + g;
    const float inv0 = 1.f / rowsum[(size_t)z * SDIM + i0];
    const float inv1 = 1.f / rowsum[(size_t)z * SDIM + i0 + 8];
    float* a0 = attn + ((size_t)z * SDIM + i0) * SDIM;
    float* a1 = attn + ((size_t)z * SDIM + i0 + 8) * SDIM;

    const unsigned* base = e2 + ((size_t)zby * 32) * 4096 + warp * 512 + t * 128 + lane * 4;
    for (int c2 = 0; c2 <= by; ++c2) {
        const int chunk = c2 * 2 + cq;
        uint4 U = *(const uint4*)(base + (size_t)chunk * 4096);
        const int jb = (chunk >> 1) * 128 + (chunk & 1) * 64 + t * 16 + 2 * tg;
        float2 fx = __half22float2(*(__half2*)&U.x);
        float2 fy = __half22float2(*(__half2*)&U.y);
        float2 fz = __half22float2(*(__half2*)&U.z);
        float2 fw = __half22float2(*(__half2*)&U.w);
        *(float2*)(a0 + jb)     = make_float2(fx.x * inv0, fx.y * inv0);
        *(float2*)(a1 + jb)     = make_float2(fy.x * inv1, fy.y * inv1);
        *(float2*)(a0 + jb + 8) = make_float2(fz.x * inv0, fz.y * inv0);
        *(float2*)(a1 + jb + 8) = make_float2(fw.x * inv1, fw.y * inv1);
    }

    // Zero-fill tail [L, SDIM) for this block's 16 rows.
    const int L  = (by + 1) * 128;
    const int W4 = (SDIM - L) >> 2;
    const float4 z4 = make_float4(0.f, 0.f, 0.f, 0.f);
    #pragma unroll 1
    for (int rr = 0; rr < 16; ++rr) {
        float* row = attn + ((size_t)z * SDIM + by * 128 + warp * 16 + rr) * SDIM + L;
        for (int j4 = tid; j4 < W4; j4 += 256)
            *(float4*)(row + j4 * 4) = z4;
    }
}

// ---------------------------------------------------------------------------
// Output projection: fp16 ctx A (linear), B from pre-packed image, fp32 C.
// ---------------------------------------------------------------------------
__global__ __launch_bounds__(256, 2)
void outproj_h(const unsigned* __restrict__ Ah, const unsigned* __restrict__ wimg,
               float* __restrict__ Cf)
{
    const int N = DD, Kw = DD / 2;
    const uint4* Bim = (const uint4*)(wimg + ((size_t)(3 * 8 + blockIdx.x) * 32) * 2048);

    __shared__ unsigned As[2][8 * RSTR];
    __shared__ unsigned Bs[2][8 * PSTR];

    const int tid  = threadIdx.x;
    const int lane = tid & 31;
    const int warp = tid >> 5;
    const int g    = lane >> 2;
    const int tg   = lane & 3;
    const int wm   = (warp >> 1) * 32;
    const int wn   = (warp & 1) * 64;

    const int am   = tid >> 1;
    const int akp0 = (tid & 1) << 3;

    unsigned wa[8];
    float c[16][4];
    #pragma unroll
    for (int i = 0; i < 16; ++i)
        #pragma unroll
        for (int j = 0; j < 4; ++j) c[i][j] = 0.f;

    const int mrow = blockIdx.y * 128 + am;

    {
        const unsigned* p = Ah + (size_t)mrow * Kw + akp0;
        *(uint4*)&wa[0] = *(const uint4*)p;
        *(uint4*)&wa[4] = *(const uint4*)(p + 4);
        store_w8<RSTR>(As[0], akp0, am, wa);
        uint4 b0 = Bim[tid], b1 = Bim[tid + 256];
        img_store(Bs[0], tid, b0, b1);
    }
    __syncthreads();

    for (int it = 0; it < 32; ++it) {
        const int cur = it & 1;
        const bool more = (it + 1 < 32);
        uint4 b0, b1;
        if (more) {
            const unsigned* p = Ah + (size_t)mrow * Kw + (it + 1) * 16 + akp0;
            *(uint4*)&wa[0] = *(const uint4*)p;
            *(uint4*)&wa[4] = *(const uint4*)(p + 4);
            b0 = Bim[(it + 1) * 512 + tid];
            b1 = Bim[(it + 1) * 512 + tid + 256];
        }

        #pragma unroll
        for (int s = 0; s < 2; ++s) {
            const unsigned* Ar = As[cur] + (s * 4 + tg) * RSTR + (g << 2);
            const unsigned* Br = Bs[cur] + (s * 4 + tg) * PSTR;
            uint4 A0 = *(const uint4*)(Ar + wm * 2);
            uint4 A1 = *(const uint4*)(Ar + (wm + 16) * 2);
            #pragma unroll
            for (int ni = 0; ni < 8; ++ni) {
                int w = (wn + ni * 8 + g) * 2;
                w ^= ((w >> 5) & 7) << 1;
                uint2 bv = *(const uint2*)(Br + w);
                mma_h(c[ni],     A0.x, A0.z, A0.y, A0.w, bv.x, bv.y);
                mma_h(c[8 + ni], A1.x, A1.z, A1.y, A1.w, bv.x, bv.y);
            }
        }

        if (more) {
            store_w8<RSTR>(As[1 - cur], akp0, am, wa);
            img_store(Bs[1 - cur], tid, b0, b1);
            __syncthreads();
        }
    }

    #pragma unroll
    for (int mi = 0; mi < 2; ++mi) {
        #pragma unroll
        for (int ni = 0; ni < 8; ++ni) {
            const float* cc = c[mi * 8 + ni];
            const int row = blockIdx.y * 128 + wm + mi * 16 + g;
            const int col = blockIdx.x * 128 + wn + ni * 8 + 2 * tg;
            *(float2*)&Cf[(size_t)row * N + col]       = make_float2(cc[0], cc[1]);
            *(float2*)&Cf[(size_t)(row + 8) * N + col] = make_float2(cc[2], cc[3]);
        }
    }
}

// ---------------------------------------------------------------------------
extern "C" void kernel_launch(void* const* d_in, const int* in_sizes, int n_in,
                              void* d_out, int out_size)
{
    const float* query = (const float*)d_in[0];
    const float* key   = (const float*)d_in[1];
    const float* value = (const float*)d_in[2];
    const float* wq    = (const float*)d_in[4];
    const float* wk    = (const float*)d_in[5];
    const float* wv    = (const float*)d_in[6];
    const float* wo    = (const float*)d_in[7];

    float* out  = (float*)d_out;
    float* attn = out + (size_t)BB * SDIM * DD;

    unsigned *q, *k, *v, *ctx, *e, *wimg, *aimg;
    float* rowsum;
    cudaGetSymbolAddress((void**)&q,      g_q);
    cudaGetSymbolAddress((void**)&k,      g_k);
    cudaGetSymbolAddress((void**)&v,      g_v);
    cudaGetSymbolAddress((void**)&ctx,    g_ctx);
    cudaGetSymbolAddress((void**)&e,      g_e);
    cudaGetSymbolAddress((void**)&rowsum, g_rowsum);
    cudaGetSymbolAddress((void**)&wimg,   g_wimg);
    cudaGetSymbolAddress((void**)&aimg,   g_aimg);

    const dim3 blk(256);

    // Pre-pack operands into smem-image layout (fp16).
    prepack_w<<<dim3(8, 32, 4), blk>>>(wq, wk, wv, wo, wimg);
    prepack_a<<<dim3(32, 32, 3), blk>>>(query, key, value, aimg);

    // Combined QKV projections.
    qkv_h<<<dim3(24, (BB * SDIM) / 128), blk>>>(aimg, wimg, q, k, v);

    // Fused scores+exp+context (heavy-first 1D grid).
    fused_attn<<<512, blk>>>(q, k, v, e, rowsum, ctx);

    // attn decode+normalize (+ causal zero fill).
    norm_attn<<<32 * 16 * 8, blk>>>(e, rowsum, attn);

    // Output projection.
    outproj_h<<<dim3(DD / 128, (BB * SDIM) / 128), blk>>>(ctx, wimg, out);
}